// round 14
// baseline (speedup 1.0000x reference)
#include <cuda_runtime.h>
#include <cuda_fp16.h>
#include <math.h>
#include <stdint.h>

#define B_    16
#define S_    2048
#define D_    1024
#define H_    16
#define P_    8
#define R_    128      // H_*P_
#define HD_   64
#define SUMN  73
#define NROW  1168     // B_*SUMN
#define NROWP 1280     // padded to 10*128

// ---------------- scratch (static device globals; no allocation) ----------------
__device__ int    g_len[B_];
__device__ int    g_tcnt;
__device__ int    g_tiles[B_ * 16];
__device__ float  g_q[P_ * D_];
__device__ __half g_Ah[R_ * D_];
__device__ __half g_hidh[(size_t)B_ * S_ * D_];   // zero-init; only rows s<~len written
__device__ float  g_sc[(size_t)B_ * R_ * S_];     // scores (fp32)
__device__ __half g_sch[(size_t)B_ * R_ * S_];    // attn (half)
__device__ float  g_crp[2][(size_t)B_ * R_ * D_]; // ctxRaw split-K partials
__device__ float  g_ctxp[8][R_ * D_];
__device__ __half g_ctxh[R_ * D_];
__device__ float  g_pool[R_ * D_];
__device__ __half g_lnvh[(size_t)NROWP * D_];
__device__ __half g_lngh[(size_t)NROWP * D_];
__device__ __half g_wvh[D_ * D_];
__device__ __half g_wgh[D_ * D_];
__device__ __half g_owh[D_ * D_];
__device__ float  g_vraw[(size_t)NROW * D_];
__device__ float  g_graw[(size_t)NROW * D_];
__device__ float  g_msk[NROWP];

// ---------------- helpers ----------------
__device__ __forceinline__ uint32_t su(const void* p) {
    return (uint32_t)__cvta_generic_to_shared(p);
}
__device__ __forceinline__ void cpa16(uint32_t dst, const void* src) {
    asm volatile("cp.async.cg.shared.global [%0], [%1], 16;" :: "r"(dst), "l"(src));
}
#define CP_COMMIT() asm volatile("cp.async.commit_group;")
#define CP_WAIT1()  asm volatile("cp.async.wait_group 1;")

__device__ __forceinline__ void mma_f16(float* d, const uint32_t* a, const uint32_t* b) {
    asm volatile(
        "mma.sync.aligned.m16n8k16.row.col.f32.f16.f16.f32 "
        "{%0,%1,%2,%3}, {%4,%5,%6,%7}, {%8,%9}, {%0,%1,%2,%3};"
        : "+f"(d[0]), "+f"(d[1]), "+f"(d[2]), "+f"(d[3])
        : "r"(a[0]), "r"(a[1]), "r"(a[2]), "r"(a[3]), "r"(b[0]), "r"(b[1]));
}

__device__ __forceinline__ float blk_red_sum(float v, float* sh) {
    #pragma unroll
    for (int o = 16; o > 0; o >>= 1) v += __shfl_down_sync(0xffffffffu, v, o);
    int w = threadIdx.x >> 5, l = threadIdx.x & 31;
    __syncthreads();
    if (l == 0) sh[w] = v;
    __syncthreads();
    float r = 0.f;
    #pragma unroll
    for (int i = 0; i < 8; i++) r += sh[i];
    return r;
}
__device__ __forceinline__ float blk_red_max(float v, float* sh) {
    #pragma unroll
    for (int o = 16; o > 0; o >>= 1) v = fmaxf(v, __shfl_down_sync(0xffffffffu, v, o));
    int w = threadIdx.x >> 5, l = threadIdx.x & 31;
    __syncthreads();
    if (l == 0) sh[w] = v;
    __syncthreads();
    float r = -3.4e38f;
    #pragma unroll
    for (int i = 0; i < 8; i++) r = fmaxf(r, sh[i]);
    return r;
}

// ---------------- fp16 mma core: C[128x128] = A[128xK] . B[128xK]^T ----------------
// 256 threads, 8 warps, 64x32 warp tiles. Both operands K-major half, row stride D_.
__device__ __forceinline__ void core_h(
    const __half* __restrict__ Ar, const __half* __restrict__ Br, int NT32,
    __half sA[2][128][40], __half sB[2][128][40], float acc[4][4][4])
{
    const int tid = threadIdx.x;
    const int wid = tid >> 5, lane = tid & 31;
    const int g = lane >> 2, c = lane & 3;
    const int m0 = (wid >> 2) * 64, n0 = (wid & 3) * 32;

#define HLOAD(T, BUF) { \
    int kg = (T) * 32; \
    _Pragma("unroll") \
    for (int q = 0; q < 2; q++) { \
        int idx = tid + q * 256; \
        int row = idx >> 2, cc = idx & 3; \
        cpa16(su(&sA[BUF][row][cc * 8]), Ar + (size_t)row * D_ + kg + cc * 8); \
        cpa16(su(&sB[BUF][row][cc * 8]), Br + (size_t)row * D_ + kg + cc * 8); \
    } }

    HLOAD(0, 0); CP_COMMIT();
    for (int t = 0; t < NT32; t++) {
        int cur = t & 1;
        if (t + 1 < NT32) { HLOAD(t + 1, cur ^ 1); }
        CP_COMMIT(); CP_WAIT1(); __syncthreads();
        #pragma unroll
        for (int sub = 0; sub < 2; sub++) {
            int kb = sub * 16;
            uint32_t A4[4][4], B2[4][2];
            #pragma unroll
            for (int i = 0; i < 4; i++) {
                A4[i][0] = *(const uint32_t*)&sA[cur][m0 + i * 16 + g][kb + 2 * c];
                A4[i][1] = *(const uint32_t*)&sA[cur][m0 + i * 16 + g + 8][kb + 2 * c];
                A4[i][2] = *(const uint32_t*)&sA[cur][m0 + i * 16 + g][kb + 2 * c + 8];
                A4[i][3] = *(const uint32_t*)&sA[cur][m0 + i * 16 + g + 8][kb + 2 * c + 8];
            }
            #pragma unroll
            for (int j = 0; j < 4; j++) {
                B2[j][0] = *(const uint32_t*)&sB[cur][n0 + j * 8 + g][kb + 2 * c];
                B2[j][1] = *(const uint32_t*)&sB[cur][n0 + j * 8 + g][kb + 2 * c + 8];
            }
            #pragma unroll
            for (int i = 0; i < 4; i++)
                #pragma unroll
                for (int j = 0; j < 4; j++)
                    mma_f16(acc[i][j], A4[i], B2[j]);
        }
        __syncthreads();
    }
#undef HLOAD
}

// ---------------- K0: lengths via ballot-parallel prefix search + tile list; ONE block ----------------
__global__ void k_lentiles(const void* __restrict__ vmraw) {
    __shared__ int is_u8;
    const unsigned char* vb = (const unsigned char*)vmraw;
    const int* vi = (const int*)vmraw;
    const int tid = threadIdx.x, wid = tid >> 5, lane = tid & 31;
    if (tid == 0) {
        int ones = 0;
        #pragma unroll
        for (int i = 0; i < 16; i++) ones += (vb[i] != 0) ? 1 : 0;
        is_u8 = (ones > 4) ? 1 : 0;
    }
    __syncthreads();
    const int u8 = is_u8;
    #pragma unroll
    for (int pass = 0; pass < 2; pass++) {
        const int b = wid + pass * 8;
        const size_t boff = (size_t)b * S_;
        int p1 = lane * 64;
        int v1 = u8 ? (vb[boff + p1] != 0) : (vi[boff + p1] != 0);
        unsigned m1 = __ballot_sync(0xffffffffu, v1);
        int base = (31 - __clz(m1)) * 64;
        int p2 = base + lane * 2;
        int v2 = u8 ? (vb[boff + p2] != 0) : (vi[boff + p2] != 0);
        unsigned m2 = __ballot_sync(0xffffffffu, v2);
        base += (31 - __clz(m2)) * 2;
        int v3 = u8 ? (vb[boff + base + 1] != 0) : (vi[boff + base + 1] != 0);
        if (lane == 0) g_len[b] = base + 1 + (v3 ? 1 : 0);
    }
    __syncthreads();
    if (tid == 0) {
        int cnt = 0;
        for (int t = 0; t < 16; t++)
            for (int bb = 0; bb < B_; bb++)
                if (t * 128 < g_len[bb]) g_tiles[cnt++] = (bb << 4) | t;
        g_tcnt = cnt;
    }
}

// ---------------- K1: q = queries @ Wq^T + bq ----------------
__global__ void k_q(const float* __restrict__ qry, const float* __restrict__ w,
                    const float* __restrict__ bia) {
    int wid = (blockIdx.x * 256 + threadIdx.x) >> 5;
    int l = threadIdx.x & 31;
    int p = wid >> 10;
    int j = wid & 1023;
    const float* qr = qry + (size_t)p * D_;
    const float* wr = w + (size_t)j * D_;
    float s = 0.f;
    for (int e = l; e < D_; e += 32) s += qr[e] * wr[e];
    #pragma unroll
    for (int o = 16; o > 0; o >>= 1) s += __shfl_down_sync(0xffffffffu, s, o);
    if (l == 0) g_q[p * D_ + j] = s + bia[j];
}

// ---------------- K2: A[r][e] = (1/8) * sum_d q[p][h*64+d] * Wk[h*64+d][e] -> half ----------------
__global__ void k_A(const float* __restrict__ w) {
    int idx = blockIdx.x * 256 + threadIdx.x;
    int r = idx >> 10, e = idx & 1023;
    int h = r >> 3, p = r & 7;
    const float* qrow = g_q + p * D_ + h * HD_;
    const float* wr = w + (size_t)(D_ + h * HD_) * D_ + e;
    float s = 0.f;
    #pragma unroll 8
    for (int d = 0; d < HD_; d++) s += qrow[d] * wr[(size_t)d * D_];
    g_Ah[idx] = __float2half_rn(0.125f * s);
}

// ---------------- K2b: convert W_v / W_g / out_w to half (8 elems/thread) ----------------
__global__ void k_cvtW(const float* __restrict__ wv, const float* __restrict__ wg,
                       const float* __restrict__ ow) {
    int i = (blockIdx.x * 256 + threadIdx.x) * 8;
    #pragma unroll
    for (int u = 0; u < 2; u++) {
        float4 a = *(const float4*)(wv + i + u * 4);
        float4 b = *(const float4*)(wg + i + u * 4);
        float4 o = *(const float4*)(ow + i + u * 4);
        __half2* dv = (__half2*)(g_wvh + i + u * 4);
        __half2* dg = (__half2*)(g_wgh + i + u * 4);
        __half2* doo = (__half2*)(g_owh + i + u * 4);
        dv[0] = __floats2half2_rn(a.x, a.y); dv[1] = __floats2half2_rn(a.z, a.w);
        dg[0] = __floats2half2_rn(b.x, b.y); dg[1] = __floats2half2_rn(b.z, b.w);
        doo[0] = __floats2half2_rn(o.x, o.y); doo[1] = __floats2half2_rn(o.z, o.w);
    }
}

// ---------------- K2c: convert hidden to half; guard probes MASK directly (no g_len dep) ----------------
// prefix mask: s0 < len[b]  <=>  mask[b*S + s0] valid. Boundary blocks may convert
// up to 3 rows past len; harmless (finite data, only ever multiplied by attn=0 or
// masked out of softmax).
__global__ void k_cvthid(const float* __restrict__ hid, const void* __restrict__ vmraw) {
    __shared__ int go;
    const int b = blockIdx.y;
    const int s0 = blockIdx.x * 4;
    if (threadIdx.x == 0) {
        const unsigned char* vb = (const unsigned char*)vmraw;
        int ones = 0;
        #pragma unroll
        for (int i = 0; i < 16; i++) ones += (vb[i] != 0) ? 1 : 0;
        if (ones > 4) {   // uint8 mask
            go = (vb[(size_t)b * S_ + s0] != 0) ? 1 : 0;
        } else {          // int32 mask
            go = (((const int*)vmraw)[(size_t)b * S_ + s0] != 0) ? 1 : 0;
        }
    }
    __syncthreads();
    if (!go) return;
    size_t base = ((size_t)b * S_ + s0) * D_;
    #pragma unroll
    for (int u = 0; u < 2; u++) {
        size_t i = base + threadIdx.x * 8 + (size_t)u * 2048;
        float4 a = *(const float4*)(hid + i);
        float4 c = *(const float4*)(hid + i + 4);
        __half2* dst = (__half2*)(g_hidh + i);
        dst[0] = __floats2half2_rn(a.x, a.y);
        dst[1] = __floats2half2_rn(a.z, a.w);
        dst[2] = __floats2half2_rn(c.x, c.y);
        dst[3] = __floats2half2_rn(c.z, c.w);
    }
}

// ---------------- K3: scores = A . hidden^T  (fp16 mma, tile-list compacted) ----------------
__global__ void __launch_bounds__(256, 2) k_scores_h() {
    __shared__ __half sA[2][128][40];
    __shared__ __half sB[2][128][40];
    if (blockIdx.x >= g_tcnt) return;
    const int tile = g_tiles[blockIdx.x];
    const int b = tile >> 4;
    const int s0 = (tile & 15) * 128;
    float acc[4][4][4];
    #pragma unroll
    for (int i = 0; i < 4; i++) for (int j = 0; j < 4; j++) for (int k = 0; k < 4; k++) acc[i][j][k] = 0.f;
    core_h(g_Ah, g_hidh + ((size_t)b * S_ + s0) * D_, 32, sA, sB, acc);
    const int lane = threadIdx.x & 31, wid = threadIdx.x >> 5;
    const int g = lane >> 2, c = lane & 3;
    const int m0 = (wid >> 2) * 64, n0 = (wid & 3) * 32;
    #pragma unroll
    for (int i = 0; i < 4; i++)
        #pragma unroll
        for (int j = 0; j < 4; j++) {
            int r = m0 + i * 16 + g;
            int s = s0 + n0 + j * 8 + 2 * c;
            *(float2*)&g_sc[((size_t)(b * R_ + r)) * S_ + s] = make_float2(acc[i][j][0], acc[i][j][1]);
            *(float2*)&g_sc[((size_t)(b * R_ + r + 8)) * S_ + s] = make_float2(acc[i][j][2], acc[i][j][3]);
        }
}

// ---------------- K4: softmax over s<len; writes half attn; zero-fills to 128 ----------------
__global__ void k_softmax() {
    __shared__ float sh[8];
    int row = blockIdx.x;
    int b = row >> 7;
    int len = g_len[b];
    size_t base = (size_t)row * S_;
    int tid = threadIdx.x;
    float v[8];
    int n = 0;
    float mx = -3.4e38f;
    for (int i = tid; i < len; i += 256) { float x = g_sc[base + i]; v[n++] = x; mx = fmaxf(mx, x); }
    float bm = blk_red_max(mx, sh);
    float s = 0.f;
    for (int k = 0; k < n; k++) { v[k] = __expf(v[k] - bm); s += v[k]; }
    float bs = blk_red_sum(s, sh);
    float inv = 1.f / bs;
    n = 0;
    for (int i = tid; i < len; i += 256) g_sch[base + i] = __float2half_rn(v[n++] * inv);
    int rend = (len + 127) & ~127;
    for (int i = len + tid; i < rend; i += 256) g_sch[base + i] = __ushort_as_half((unsigned short)0);
}

// ---------------- K5: ctxRaw = attn . hidden  (fp16 mma; B MN-major; split-K x2) ----------------
__global__ void __launch_bounds__(256, 2) k_ctxraw_h() {
    __shared__ __half sA[2][128][40];
    __shared__ __half sB[2][32][136];
    const int b = blockIdx.y;
    const int e0 = blockIdx.x * 128;
    const int ks = blockIdx.z;
    const int len = g_len[b];
    const int NT32 = (len + 31) >> 5;
    const int t0 = ks * 32;
    const int t1 = (NT32 < t0 + 32) ? NT32 : (t0 + 32);
    const int tid = threadIdx.x;
    const int wid = tid >> 5, lane = tid & 31;
    const int g = lane >> 2, c = lane & 3;
    const int m0 = (wid >> 2) * 64, n0 = (wid & 3) * 32;
    const __half* hb = g_hidh + (size_t)b * S_ * D_;
    const __half* ab = g_sch + ((size_t)b * R_) * S_;
    float acc[4][4][4];
    #pragma unroll
    for (int i = 0; i < 4; i++) for (int j = 0; j < 4; j++) for (int k = 0; k < 4; k++) acc[i][j][k] = 0.f;

#define CLOAD(T, BUF) { \
    int kg = (T) * 32; \
    _Pragma("unroll") \
    for (int q = 0; q < 2; q++) { \
        int idx = tid + q * 256; \
        int ar = idx >> 2, ac = idx & 3; \
        cpa16(su(&sA[BUF][ar][ac * 8]), ab + (size_t)ar * S_ + kg + ac * 8); \
        int br = idx >> 4, bc = idx & 15; \
        cpa16(su(&sB[BUF][br][bc * 8]), hb + (size_t)(kg + br) * D_ + e0 + bc * 8); \
    } }

    if (t0 < t1) {
        CLOAD(t0, 0); CP_COMMIT();
        for (int t = t0; t < t1; t++) {
            int cur = (t - t0) & 1;
            if (t + 1 < t1) { CLOAD(t + 1, cur ^ 1); }
            CP_COMMIT(); CP_WAIT1(); __syncthreads();
            #pragma unroll
            for (int sub = 0; sub < 2; sub++) {
                int kb = sub * 16;
                uint32_t A4[4][4], B2[4][2];
                #pragma unroll
                for (int i = 0; i < 4; i++) {
                    A4[i][0] = *(const uint32_t*)&sA[cur][m0 + i * 16 + g][kb + 2 * c];
                    A4[i][1] = *(const uint32_t*)&sA[cur][m0 + i * 16 + g + 8][kb + 2 * c];
                    A4[i][2] = *(const uint32_t*)&sA[cur][m0 + i * 16 + g][kb + 2 * c + 8];
                    A4[i][3] = *(const uint32_t*)&sA[cur][m0 + i * 16 + g + 8][kb + 2 * c + 8];
                }
                #pragma unroll
                for (int j = 0; j < 4; j++) {
                    int n = n0 + j * 8 + g;
                    B2[j][0] = (uint32_t)__half_as_ushort(sB[cur][kb + 2 * c][n])
                             | ((uint32_t)__half_as_ushort(sB[cur][kb + 2 * c + 1][n]) << 16);
                    B2[j][1] = (uint32_t)__half_as_ushort(sB[cur][kb + 2 * c + 8][n])
                             | ((uint32_t)__half_as_ushort(sB[cur][kb + 2 * c + 9][n]) << 16);
                }
                #pragma unroll
                for (int i = 0; i < 4; i++)
                    #pragma unroll
                    for (int j = 0; j < 4; j++)
                        mma_f16(acc[i][j], A4[i], B2[j]);
            }
            __syncthreads();
        }
    }
#undef CLOAD
    float* crp = g_crp[ks];
    #pragma unroll
    for (int i = 0; i < 4; i++)
        #pragma unroll
        for (int j = 0; j < 4; j++) {
            int r = m0 + i * 16 + g;
            int e = e0 + n0 + j * 8 + 2 * c;
            *(float2*)&crp[((size_t)(b * R_ + r)) * D_ + e] = make_float2(acc[i][j][0], acc[i][j][1]);
            *(float2*)&crp[((size_t)(b * R_ + r + 8)) * D_ + e] = make_float2(acc[i][j][2], acc[i][j][3]);
        }
}

// ---------------- K6: ctx per head (FFMA k-split; A = sum of split-K partials) ----------------
__global__ void k_ctx(const float* __restrict__ w) {
    const int h = blockIdx.x;
    const int ks = blockIdx.y;
    const int tid = threadIdx.x;
    __shared__ float As[8][132];
    __shared__ float Bs[8][68];
    float acc[8][4];
    #pragma unroll
    for (int i = 0; i < 8; i++) for (int j = 0; j < 4; j++) acc[i][j] = 0.f;
    const int lm = tid >> 1;
    const int lq = (tid & 1) * 4;
    const int ln_ = tid >> 2;
    const int lq2 = (tid & 3) * 2;
    const int ty = tid >> 4;
    const int tx = tid & 15;
    const int bA = lm >> 3, pA = lm & 7;
    const size_t arow = ((size_t)(bA * R_ + h * P_ + pA)) * D_;
    const size_t wrow = (size_t)(2 * D_ + h * HD_ + ln_) * D_;
    for (int k0 = ks * 128; k0 < ks * 128 + 128; k0 += 8) {
        float4 a0 = *(const float4*)&g_crp[0][arow + k0 + lq];
        float4 a1 = *(const float4*)&g_crp[1][arow + k0 + lq];
        float2 wv = *(const float2*)&w[wrow + k0 + lq2];
        __syncthreads();
        As[lq + 0][lm] = a0.x + a1.x; As[lq + 1][lm] = a0.y + a1.y;
        As[lq + 2][lm] = a0.z + a1.z; As[lq + 3][lm] = a0.w + a1.w;
        Bs[lq2 + 0][ln_] = wv.x; Bs[lq2 + 1][ln_] = wv.y;
        __syncthreads();
        #pragma unroll
        for (int kk = 0; kk < 8; kk++) {
            float a[8], bb[4];
            #pragma unroll
            for (int i = 0; i < 8; i++) a[i] = As[kk][ty * 8 + i];
            #pragma unroll
            for (int j = 0; j < 4; j++) bb[j] = Bs[kk][tx * 4 + j];
            #pragma unroll
            for (int i = 0; i < 8; i++)
                #pragma unroll
                for (int j = 0; j < 4; j++) acc[i][j] = fmaf(a[i], bb[j], acc[i][j]);
        }
    }
    #pragma unroll
    for (int i = 0; i < 8; i++) {
        int m = ty * 8 + i;
        *(float4*)&g_ctxp[ks][(size_t)m * D_ + h * HD_ + tx * 4] =
            make_float4(acc[i][0], acc[i][1], acc[i][2], acc[i][3]);
    }
}

// ---------------- K6b: reduce partials + bias -> half ctx ----------------
__global__ void k_ctxred(const float* __restrict__ ipb) {
    int idx = blockIdx.x * 256 + threadIdx.x;
    float s = ipb[2 * D_ + (idx & 1023)];
    #pragma unroll
    for (int ks = 0; ks < 8; ks++) s += g_ctxp[ks][idx];
    g_ctxh[idx] = __float2half_rn(s);
}

// ---------------- K7: pooled = ctx @ out_w^T + ob  (fp16 mma core) ----------------
__global__ void __launch_bounds__(256, 2) k_pool_h(const float* __restrict__ ob) {
    __shared__ __half sA[2][128][40];
    __shared__ __half sB[2][128][40];
    const int f0 = blockIdx.x * 128;
    float acc[4][4][4];
    #pragma unroll
    for (int i = 0; i < 4; i++) for (int j = 0; j < 4; j++) for (int k = 0; k < 4; k++) acc[i][j][k] = 0.f;
    core_h(g_ctxh, g_owh + (size_t)f0 * D_, 32, sA, sB, acc);
    const int lane = threadIdx.x & 31, wid = threadIdx.x >> 5;
    const int g = lane >> 2, c = lane & 3;
    const int m0 = (wid >> 2) * 64, n0 = (wid & 3) * 32;
    #pragma unroll
    for (int i = 0; i < 4; i++)
        #pragma unroll
        for (int j = 0; j < 4; j++) {
            int m = m0 + i * 16 + g;
            int f = f0 + n0 + j * 8 + 2 * c;
            float b0 = ob[f], b1 = ob[f + 1];
            *(float2*)&g_pool[(size_t)m * D_ + f] = make_float2(acc[i][j][0] + b0, acc[i][j][1] + b1);
            *(float2*)&g_pool[(size_t)(m + 8) * D_ + f] = make_float2(acc[i][j][2] + b0, acc[i][j][3] + b1);
        }
}

// ---------------- K8: summary rows + LayerNorms -> half lnv/lng + mask ----------------
__global__ void k_sum(const float* __restrict__ hid,
                      const float* __restrict__ qry,
                      const float* __restrict__ pg, const float* __restrict__ pb,
                      const float* __restrict__ vg, const float* __restrict__ vb,
                      const float* __restrict__ gg, const float* __restrict__ gb) {
    __shared__ float sh[8];
    const int row = blockIdx.x;
    const int tid = threadIdx.x;
    const int j = tid * 4;
    if (row >= NROW) {
        __half2* pv = (__half2*)&g_lnvh[(size_t)row * D_ + j];
        __half2* pgp = (__half2*)&g_lngh[(size_t)row * D_ + j];
        __half2 z = __floats2half2_rn(0.f, 0.f);
        pv[0] = z; pv[1] = z; pgp[0] = z; pgp[1] = z;
        if (tid == 0) g_msk[row] = 0.f;
        return;
    }
    const int b = row / 73, t = row % 73;
    const int len = g_len[b];
    float x[4] = {0.f, 0.f, 0.f, 0.f};
    float msk = 0.f;
    bool ln1 = false;
    if (t == 0) {
        float4 v = *(const float4*)&hid[(size_t)b * S_ * D_ + j];
        x[0] = v.x; x[1] = v.y; x[2] = v.z; x[3] = v.w;
        msk = 1.f;
    } else if (t < 9) {
        int p = t - 1;
        float4 qv = *(const float4*)&qry[(size_t)p * D_ + j];
        float4 pv = *(const float4*)&g_pool[(size_t)(b * P_ + p) * D_ + j];
        x[0] = qv.x + pv.x; x[1] = qv.y + pv.y; x[2] = qv.z + pv.z; x[3] = qv.w + pv.w;
        ln1 = true;
        msk = 1.f;
    } else {
        int s = len - 64 + (t - 9);
        if (s >= 1) {
            float4 v = *(const float4*)&hid[((size_t)b * S_ + s) * D_ + j];
            x[0] = v.x; x[1] = v.y; x[2] = v.z; x[3] = v.w;
            msk = 1.f;
        }
    }
    if (ln1) {
        float sm = blk_red_sum(x[0] + x[1] + x[2] + x[3], sh);
        float mu = sm * (1.f / (float)D_);
        float d0 = x[0] - mu, d1 = x[1] - mu, d2 = x[2] - mu, d3 = x[3] - mu;
        float vq = blk_red_sum(d0 * d0 + d1 * d1 + d2 * d2 + d3 * d3, sh);
        float inv = rsqrtf(vq * (1.f / (float)D_) + 1e-5f);
        #pragma unroll
        for (int c = 0; c < 4; c++) x[c] = (x[c] - mu) * inv * pg[j + c] + pb[j + c];
    }
    float sm = blk_red_sum(x[0] + x[1] + x[2] + x[3], sh);
    float mu = sm * (1.f / (float)D_);
    float d0 = x[0] - mu, d1 = x[1] - mu, d2 = x[2] - mu, d3 = x[3] - mu;
    float vq = blk_red_sum(d0 * d0 + d1 * d1 + d2 * d2 + d3 * d3, sh);
    float inv = rsqrtf(vq * (1.f / (float)D_) + 1e-5f);
    float n0 = (x[0] - mu) * inv, n1 = (x[1] - mu) * inv, n2 = (x[2] - mu) * inv, n3 = (x[3] - mu) * inv;
    __half2* pv = (__half2*)&g_lnvh[(size_t)row * D_ + j];
    __half2* pgp = (__half2*)&g_lngh[(size_t)row * D_ + j];
    pv[0] = __floats2half2_rn(n0 * vg[j] + vb[j], n1 * vg[j + 1] + vb[j + 1]);
    pv[1] = __floats2half2_rn(n2 * vg[j + 2] + vb[j + 2], n3 * vg[j + 3] + vb[j + 3]);
    pgp[0] = __floats2half2_rn(n0 * gg[j] + gb[j], n1 * gg[j + 1] + gb[j + 1]);
    pgp[1] = __floats2half2_rn(n2 * gg[j + 2] + gb[j + 2], n3 * gg[j + 3] + gb[j + 3]);
    if (tid == 0) g_msk[row] = msk;
}

// ---------------- K9: val/gate GEMMs (fp16 mma core) ----------------
__global__ void __launch_bounds__(256, 2) k_vg_h(const float* __restrict__ bvv, const float* __restrict__ bgg) {
    __shared__ __half sA[2][128][40];
    __shared__ __half sB[2][128][40];
    const int which = blockIdx.z;
    const int r0 = blockIdx.x * 128;
    const int f0 = blockIdx.y * 128;
    const __half* Am = which ? g_lngh : g_lnvh;
    const __half* W  = which ? g_wgh : g_wvh;
    const float* bias = which ? bgg : bvv;
    float* out = which ? g_graw : g_vraw;
    float acc[4][4][4];
    #pragma unroll
    for (int i = 0; i < 4; i++) for (int j = 0; j < 4; j++) for (int k = 0; k < 4; k++) acc[i][j][k] = 0.f;
    core_h(Am + (size_t)r0 * D_, W + (size_t)f0 * D_, 32, sA, sB, acc);
    const int lane = threadIdx.x & 31, wid = threadIdx.x >> 5;
    const int g = lane >> 2, c = lane & 3;
    const int m0 = (wid >> 2) * 64, n0 = (wid & 3) * 32;
    #pragma unroll
    for (int i = 0; i < 4; i++)
        #pragma unroll
        for (int j = 0; j < 4; j++) {
            int r = r0 + m0 + i * 16 + g;
            int f = f0 + n0 + j * 8 + 2 * c;
            float b0 = bias[f], b1 = bias[f + 1];
            if (r < NROW)
                *(float2*)&out[(size_t)r * D_ + f] = make_float2(acc[i][j][0] + b0, acc[i][j][1] + b1);
            if (r + 8 < NROW)
                *(float2*)&out[(size_t)(r + 8) * D_ + f] = make_float2(acc[i][j][2] + b0, acc[i][j][3] + b1);
        }
}

// ---------------- K10: gated = silu(vraw)*sigmoid(graw)*mask -> output ----------------
__global__ void k_out(float* __restrict__ out, int write_mask) {
    int idx = blockIdx.x * 256 + threadIdx.x;
    if (idx < NROW * D_) {
        int row = idx >> 10;
        float v = g_vraw[idx], g = g_graw[idx];
        float sv = v / (1.f + __expf(-v));
        float sg = 1.f / (1.f + __expf(-g));
        out[idx] = sv * sg * g_msk[row];
    }
    if (write_mask && idx < NROW) {
        out[NROW * D_ + idx] = g_msk[idx];
    }
}

// ---------------- host launcher ----------------
extern "C" void kernel_launch(void* const* d_in, const int* in_sizes, int n_in,
                              void* d_out, int out_size) {
    (void)in_sizes; (void)n_in;
    const float* hid = (const float*)d_in[0];
    const void*  vm  = d_in[1];
    const float* qry = (const float*)d_in[2];
    const float* ipw = (const float*)d_in[3];
    const float* ipb = (const float*)d_in[4];
    const float* ow  = (const float*)d_in[5];
    const float* ob  = (const float*)d_in[6];
    const float* pg  = (const float*)d_in[7];
    const float* pb  = (const float*)d_in[8];
    const float* vg  = (const float*)d_in[9];
    const float* vb  = (const float*)d_in[10];
    const float* Wv  = (const float*)d_in[11];
    const float* bv  = (const float*)d_in[12];
    const float* gg  = (const float*)d_in[13];
    const float* gb  = (const float*)d_in[14];
    const float* Wg  = (const float*)d_in[15];
    const float* bg  = (const float*)d_in[16];
    float* out = (float*)d_out;

    // Forked-stream prep phase (joined before destruction; objects freed each call).
    // cvthid no longer depends on lentiles (probes the mask directly), so the
    // main stream starts it immediately; lentiles hides on s2 ahead of cvtW.
    cudaStream_t s1 = 0, s2 = 0;
    cudaEvent_t evRoot = 0, evA = 0, evW = 0;
    bool forked =
        cudaStreamCreateWithFlags(&s1, cudaStreamNonBlocking) == cudaSuccess &&
        cudaStreamCreateWithFlags(&s2, cudaStreamNonBlocking) == cudaSuccess &&
        cudaEventCreateWithFlags(&evRoot, cudaEventDisableTiming) == cudaSuccess &&
        cudaEventCreateWithFlags(&evA, cudaEventDisableTiming) == cudaSuccess &&
        cudaEventCreateWithFlags(&evW, cudaEventDisableTiming) == cudaSuccess;

    if (forked) {
        cudaEventRecord(evRoot, 0);
        cudaStreamWaitEvent(s1, evRoot, 0);
        cudaStreamWaitEvent(s2, evRoot, 0);
        k_q<<<1024, 256, 0, s1>>>(qry, ipw, ipb);
        k_A<<<512, 256, 0, s1>>>(ipw);
        cudaEventRecord(evA, s1);
        k_lentiles<<<1, 256, 0, s2>>>(vm);
        k_cvtW<<<512, 256, 0, s2>>>(Wv, Wg, ow);
        cudaEventRecord(evW, s2);
        k_cvthid<<<dim3(512, 16), 256>>>(hid, vm);
        cudaStreamWaitEvent(0, evA, 0);
        cudaStreamWaitEvent(0, evW, 0);
    } else {
        k_lentiles<<<1, 256>>>(vm);
        k_q<<<1024, 256>>>(qry, ipw, ipb);
        k_A<<<512, 256>>>(ipw);
        k_cvtW<<<512, 256>>>(Wv, Wg, ow);
        k_cvthid<<<dim3(512, 16), 256>>>(hid, vm);
    }

    k_scores_h<<<256, 256>>>();
    k_softmax<<<B_ * R_, 256>>>();
    k_ctxraw_h<<<dim3(8, 16, 2), 256>>>();
    k_ctx<<<dim3(16, 8), 256>>>(ipw);
    k_ctxred<<<512, 256>>>(ipb);
    k_pool_h<<<8, 256>>>(ob);
    k_sum<<<NROWP, 256>>>(hid, qry, pg, pb, vg, vb, gg, gb);
    k_vg_h<<<dim3(10, 8, 2), 256>>>(bv, bg);
    int wm = (out_size >= NROW * D_ + NROW) ? 1 : 0;
    k_out<<<(NROW * D_ + 255) / 256, 256>>>(out, wm);

    if (s1) cudaStreamDestroy(s1);
    if (s2) cudaStreamDestroy(s2);
    if (evRoot) cudaEventDestroy(evRoot);
    if (evA) cudaEventDestroy(evA);
    if (evW) cudaEventDestroy(evW);
}

// round 15
// speedup vs baseline: 1.0130x; 1.0130x over previous
#include <cuda_runtime.h>
#include <cuda_fp16.h>
#include <math.h>
#include <stdint.h>

#define B_    16
#define S_    2048
#define D_    1024
#define H_    16
#define P_    8
#define R_    128      // H_*P_
#define HD_   64
#define SUMN  73
#define NROW  1168     // B_*SUMN
#define NROWP 1280     // padded to 10*128

// ---------------- scratch (static device globals; no allocation) ----------------
__device__ int    g_len[B_];
__device__ int    g_tcnt;
__device__ int    g_tiles[B_ * 16];
__device__ float  g_q[P_ * D_];
__device__ __half g_Ah[R_ * D_];
__device__ __half g_hidh[(size_t)B_ * S_ * D_];   // zero-init; only rows s<len written
__device__ float  g_sc[(size_t)B_ * R_ * S_];     // scores (fp32)
__device__ __half g_sch[(size_t)B_ * R_ * S_];    // attn (half)
__device__ __half g_crph[2][(size_t)B_ * R_ * D_]; // ctxRaw split-K partials (half)
__device__ float  g_ctxp[8][R_ * D_];
__device__ __half g_ctxh[R_ * D_];
__device__ float  g_pool[R_ * D_];
__device__ __half g_lnvh[(size_t)NROWP * D_];
__device__ __half g_lngh[(size_t)NROWP * D_];
__device__ __half g_wvh[D_ * D_];
__device__ __half g_wgh[D_ * D_];
__device__ __half g_owh[D_ * D_];
__device__ float  g_vraw[(size_t)NROW * D_];
__device__ float  g_graw[(size_t)NROW * D_];
__device__ float  g_msk[NROWP];

// ---------------- helpers ----------------
__device__ __forceinline__ uint32_t su(const void* p) {
    return (uint32_t)__cvta_generic_to_shared(p);
}
__device__ __forceinline__ void cpa16(uint32_t dst, const void* src) {
    asm volatile("cp.async.cg.shared.global [%0], [%1], 16;" :: "r"(dst), "l"(src));
}
#define CP_COMMIT() asm volatile("cp.async.commit_group;")
#define CP_WAIT1()  asm volatile("cp.async.wait_group 1;")

__device__ __forceinline__ void mma_f16(float* d, const uint32_t* a, const uint32_t* b) {
    asm volatile(
        "mma.sync.aligned.m16n8k16.row.col.f32.f16.f16.f32 "
        "{%0,%1,%2,%3}, {%4,%5,%6,%7}, {%8,%9}, {%0,%1,%2,%3};"
        : "+f"(d[0]), "+f"(d[1]), "+f"(d[2]), "+f"(d[3])
        : "r"(a[0]), "r"(a[1]), "r"(a[2]), "r"(a[3]), "r"(b[0]), "r"(b[1]));
}

__device__ __forceinline__ float blk_red_sum(float v, float* sh) {
    #pragma unroll
    for (int o = 16; o > 0; o >>= 1) v += __shfl_down_sync(0xffffffffu, v, o);
    int w = threadIdx.x >> 5, l = threadIdx.x & 31;
    __syncthreads();
    if (l == 0) sh[w] = v;
    __syncthreads();
    float r = 0.f;
    #pragma unroll
    for (int i = 0; i < 8; i++) r += sh[i];
    return r;
}
__device__ __forceinline__ float blk_red_max(float v, float* sh) {
    #pragma unroll
    for (int o = 16; o > 0; o >>= 1) v = fmaxf(v, __shfl_down_sync(0xffffffffu, v, o));
    int w = threadIdx.x >> 5, l = threadIdx.x & 31;
    __syncthreads();
    if (l == 0) sh[w] = v;
    __syncthreads();
    float r = -3.4e38f;
    #pragma unroll
    for (int i = 0; i < 8; i++) r = fmaxf(r, sh[i]);
    return r;
}

// ---------------- fp16 mma core: C[128x128] = A[128xK] . B[128xK]^T ----------------
// 256 threads, 8 warps, 64x32 warp tiles. Both operands K-major half, row stride D_.
__device__ __forceinline__ void core_h(
    const __half* __restrict__ Ar, const __half* __restrict__ Br, int NT32,
    __half sA[2][128][40], __half sB[2][128][40], float acc[4][4][4])
{
    const int tid = threadIdx.x;
    const int wid = tid >> 5, lane = tid & 31;
    const int g = lane >> 2, c = lane & 3;
    const int m0 = (wid >> 2) * 64, n0 = (wid & 3) * 32;

#define HLOAD(T, BUF) { \
    int kg = (T) * 32; \
    _Pragma("unroll") \
    for (int q = 0; q < 2; q++) { \
        int idx = tid + q * 256; \
        int row = idx >> 2, cc = idx & 3; \
        cpa16(su(&sA[BUF][row][cc * 8]), Ar + (size_t)row * D_ + kg + cc * 8); \
        cpa16(su(&sB[BUF][row][cc * 8]), Br + (size_t)row * D_ + kg + cc * 8); \
    } }

    HLOAD(0, 0); CP_COMMIT();
    for (int t = 0; t < NT32; t++) {
        int cur = t & 1;
        if (t + 1 < NT32) { HLOAD(t + 1, cur ^ 1); }
        CP_COMMIT(); CP_WAIT1(); __syncthreads();
        #pragma unroll
        for (int sub = 0; sub < 2; sub++) {
            int kb = sub * 16;
            uint32_t A4[4][4], B2[4][2];
            #pragma unroll
            for (int i = 0; i < 4; i++) {
                A4[i][0] = *(const uint32_t*)&sA[cur][m0 + i * 16 + g][kb + 2 * c];
                A4[i][1] = *(const uint32_t*)&sA[cur][m0 + i * 16 + g + 8][kb + 2 * c];
                A4[i][2] = *(const uint32_t*)&sA[cur][m0 + i * 16 + g][kb + 2 * c + 8];
                A4[i][3] = *(const uint32_t*)&sA[cur][m0 + i * 16 + g + 8][kb + 2 * c + 8];
            }
            #pragma unroll
            for (int j = 0; j < 4; j++) {
                B2[j][0] = *(const uint32_t*)&sB[cur][n0 + j * 8 + g][kb + 2 * c];
                B2[j][1] = *(const uint32_t*)&sB[cur][n0 + j * 8 + g][kb + 2 * c + 8];
            }
            #pragma unroll
            for (int i = 0; i < 4; i++)
                #pragma unroll
                for (int j = 0; j < 4; j++)
                    mma_f16(acc[i][j], A4[i], B2[j]);
        }
        __syncthreads();
    }
#undef HLOAD
}

// ---------------- K0: lengths via ballot-parallel prefix search + tile list; ONE block ----------------
__global__ void k_lentiles(const void* __restrict__ vmraw) {
    __shared__ int is_u8;
    const unsigned char* vb = (const unsigned char*)vmraw;
    const int* vi = (const int*)vmraw;
    const int tid = threadIdx.x, wid = tid >> 5, lane = tid & 31;
    if (tid == 0) {
        int ones = 0;
        #pragma unroll
        for (int i = 0; i < 16; i++) ones += (vb[i] != 0) ? 1 : 0;
        is_u8 = (ones > 4) ? 1 : 0;
    }
    __syncthreads();
    const int u8 = is_u8;
    #pragma unroll
    for (int pass = 0; pass < 2; pass++) {
        const int b = wid + pass * 8;
        const size_t boff = (size_t)b * S_;
        int p1 = lane * 64;
        int v1 = u8 ? (vb[boff + p1] != 0) : (vi[boff + p1] != 0);
        unsigned m1 = __ballot_sync(0xffffffffu, v1);
        int base = (31 - __clz(m1)) * 64;
        int p2 = base + lane * 2;
        int v2 = u8 ? (vb[boff + p2] != 0) : (vi[boff + p2] != 0);
        unsigned m2 = __ballot_sync(0xffffffffu, v2);
        base += (31 - __clz(m2)) * 2;
        int v3 = u8 ? (vb[boff + base + 1] != 0) : (vi[boff + base + 1] != 0);
        if (lane == 0) g_len[b] = base + 1 + (v3 ? 1 : 0);
    }
    __syncthreads();
    if (tid == 0) {
        int cnt = 0;
        for (int t = 0; t < 16; t++)
            for (int bb = 0; bb < B_; bb++)
                if (t * 128 < g_len[bb]) g_tiles[cnt++] = (bb << 4) | t;
        g_tcnt = cnt;
    }
}

// ---------------- K1: q = queries @ Wq^T + bq ----------------
__global__ void k_q(const float* __restrict__ qry, const float* __restrict__ w,
                    const float* __restrict__ bia) {
    int wid = (blockIdx.x * 256 + threadIdx.x) >> 5;
    int l = threadIdx.x & 31;
    int p = wid >> 10;
    int j = wid & 1023;
    const float* qr = qry + (size_t)p * D_;
    const float* wr = w + (size_t)j * D_;
    float s = 0.f;
    for (int e = l; e < D_; e += 32) s += qr[e] * wr[e];
    #pragma unroll
    for (int o = 16; o > 0; o >>= 1) s += __shfl_down_sync(0xffffffffu, s, o);
    if (l == 0) g_q[p * D_ + j] = s + bia[j];
}

// ---------------- K2: A[r][e] = (1/8) * sum_d q[p][h*64+d] * Wk[h*64+d][e] -> half ----------------
__global__ void k_A(const float* __restrict__ w) {
    int idx = blockIdx.x * 256 + threadIdx.x;
    int r = idx >> 10, e = idx & 1023;
    int h = r >> 3, p = r & 7;
    const float* qrow = g_q + p * D_ + h * HD_;
    const float* wr = w + (size_t)(D_ + h * HD_) * D_ + e;
    float s = 0.f;
    #pragma unroll 8
    for (int d = 0; d < HD_; d++) s += qrow[d] * wr[(size_t)d * D_];
    g_Ah[idx] = __float2half_rn(0.125f * s);
}

// ---------------- K2b: convert W_v / W_g / out_w to half (8 elems/thread) ----------------
__global__ void k_cvtW(const float* __restrict__ wv, const float* __restrict__ wg,
                       const float* __restrict__ ow) {
    int i = (blockIdx.x * 256 + threadIdx.x) * 8;
    #pragma unroll
    for (int u = 0; u < 2; u++) {
        float4 a = *(const float4*)(wv + i + u * 4);
        float4 b = *(const float4*)(wg + i + u * 4);
        float4 o = *(const float4*)(ow + i + u * 4);
        __half2* dv = (__half2*)(g_wvh + i + u * 4);
        __half2* dg = (__half2*)(g_wgh + i + u * 4);
        __half2* doo = (__half2*)(g_owh + i + u * 4);
        dv[0] = __floats2half2_rn(a.x, a.y); dv[1] = __floats2half2_rn(a.z, a.w);
        dg[0] = __floats2half2_rn(b.x, b.y); dg[1] = __floats2half2_rn(b.z, b.w);
        doo[0] = __floats2half2_rn(o.x, o.y); doo[1] = __floats2half2_rn(o.z, o.w);
    }
}

// ---------------- K2c: convert hidden to half, ONLY rows s < len[b] (4 rows/block) ----------------
__global__ void k_cvthid(const float* __restrict__ hid) {
    const int b = blockIdx.y;
    const int s0 = blockIdx.x * 4;
    if (s0 >= g_len[b]) return;
    size_t base = ((size_t)b * S_ + s0) * D_;
    #pragma unroll
    for (int u = 0; u < 2; u++) {
        size_t i = base + threadIdx.x * 8 + (size_t)u * 2048;
        float4 a = *(const float4*)(hid + i);
        float4 c = *(const float4*)(hid + i + 4);
        __half2* dst = (__half2*)(g_hidh + i);
        dst[0] = __floats2half2_rn(a.x, a.y);
        dst[1] = __floats2half2_rn(a.z, a.w);
        dst[2] = __floats2half2_rn(c.x, c.y);
        dst[3] = __floats2half2_rn(c.z, c.w);
    }
}

// ---------------- K3: scores = A . hidden^T  (fp16 mma, tile-list compacted) ----------------
__global__ void __launch_bounds__(256, 2) k_scores_h() {
    __shared__ __half sA[2][128][40];
    __shared__ __half sB[2][128][40];
    if (blockIdx.x >= g_tcnt) return;
    const int tile = g_tiles[blockIdx.x];
    const int b = tile >> 4;
    const int s0 = (tile & 15) * 128;
    float acc[4][4][4];
    #pragma unroll
    for (int i = 0; i < 4; i++) for (int j = 0; j < 4; j++) for (int k = 0; k < 4; k++) acc[i][j][k] = 0.f;
    core_h(g_Ah, g_hidh + ((size_t)b * S_ + s0) * D_, 32, sA, sB, acc);
    const int lane = threadIdx.x & 31, wid = threadIdx.x >> 5;
    const int g = lane >> 2, c = lane & 3;
    const int m0 = (wid >> 2) * 64, n0 = (wid & 3) * 32;
    #pragma unroll
    for (int i = 0; i < 4; i++)
        #pragma unroll
        for (int j = 0; j < 4; j++) {
            int r = m0 + i * 16 + g;
            int s = s0 + n0 + j * 8 + 2 * c;
            *(float2*)&g_sc[((size_t)(b * R_ + r)) * S_ + s] = make_float2(acc[i][j][0], acc[i][j][1]);
            *(float2*)&g_sc[((size_t)(b * R_ + r + 8)) * S_ + s] = make_float2(acc[i][j][2], acc[i][j][3]);
        }
}

// ---------------- K4: softmax over s<len; writes half attn; zero-fills to 128 ----------------
__global__ void k_softmax() {
    __shared__ float sh[8];
    int row = blockIdx.x;
    int b = row >> 7;
    int len = g_len[b];
    size_t base = (size_t)row * S_;
    int tid = threadIdx.x;
    float v[8];
    int n = 0;
    float mx = -3.4e38f;
    for (int i = tid; i < len; i += 256) { float x = g_sc[base + i]; v[n++] = x; mx = fmaxf(mx, x); }
    float bm = blk_red_max(mx, sh);
    float s = 0.f;
    for (int k = 0; k < n; k++) { v[k] = __expf(v[k] - bm); s += v[k]; }
    float bs = blk_red_sum(s, sh);
    float inv = 1.f / bs;
    n = 0;
    for (int i = tid; i < len; i += 256) g_sch[base + i] = __float2half_rn(v[n++] * inv);
    int rend = (len + 127) & ~127;
    for (int i = len + tid; i < rend; i += 256) g_sch[base + i] = __ushort_as_half((unsigned short)0);
}

// ---------------- K5: ctxRaw = attn . hidden  (fp16 mma; B MN-major; split-K x2; half partials) ----------------
__global__ void __launch_bounds__(256, 2) k_ctxraw_h() {
    __shared__ __half sA[2][128][40];
    __shared__ __half sB[2][32][136];
    const int b = blockIdx.y;
    const int e0 = blockIdx.x * 128;
    const int ks = blockIdx.z;
    const int len = g_len[b];
    const int NT32 = (len + 31) >> 5;
    const int t0 = ks * 32;
    const int t1 = (NT32 < t0 + 32) ? NT32 : (t0 + 32);
    const int tid = threadIdx.x;
    const int wid = tid >> 5, lane = tid & 31;
    const int g = lane >> 2, c = lane & 3;
    const int m0 = (wid >> 2) * 64, n0 = (wid & 3) * 32;
    const __half* hb = g_hidh + (size_t)b * S_ * D_;
    const __half* ab = g_sch + ((size_t)b * R_) * S_;
    float acc[4][4][4];
    #pragma unroll
    for (int i = 0; i < 4; i++) for (int j = 0; j < 4; j++) for (int k = 0; k < 4; k++) acc[i][j][k] = 0.f;

#define CLOAD(T, BUF) { \
    int kg = (T) * 32; \
    _Pragma("unroll") \
    for (int q = 0; q < 2; q++) { \
        int idx = tid + q * 256; \
        int ar = idx >> 2, ac = idx & 3; \
        cpa16(su(&sA[BUF][ar][ac * 8]), ab + (size_t)ar * S_ + kg + ac * 8); \
        int br = idx >> 4, bc = idx & 15; \
        cpa16(su(&sB[BUF][br][bc * 8]), hb + (size_t)(kg + br) * D_ + e0 + bc * 8); \
    } }

    if (t0 < t1) {
        CLOAD(t0, 0); CP_COMMIT();
        for (int t = t0; t < t1; t++) {
            int cur = (t - t0) & 1;
            if (t + 1 < t1) { CLOAD(t + 1, cur ^ 1); }
            CP_COMMIT(); CP_WAIT1(); __syncthreads();
            #pragma unroll
            for (int sub = 0; sub < 2; sub++) {
                int kb = sub * 16;
                uint32_t A4[4][4], B2[4][2];
                #pragma unroll
                for (int i = 0; i < 4; i++) {
                    A4[i][0] = *(const uint32_t*)&sA[cur][m0 + i * 16 + g][kb + 2 * c];
                    A4[i][1] = *(const uint32_t*)&sA[cur][m0 + i * 16 + g + 8][kb + 2 * c];
                    A4[i][2] = *(const uint32_t*)&sA[cur][m0 + i * 16 + g][kb + 2 * c + 8];
                    A4[i][3] = *(const uint32_t*)&sA[cur][m0 + i * 16 + g + 8][kb + 2 * c + 8];
                }
                #pragma unroll
                for (int j = 0; j < 4; j++) {
                    int n = n0 + j * 8 + g;
                    B2[j][0] = (uint32_t)__half_as_ushort(sB[cur][kb + 2 * c][n])
                             | ((uint32_t)__half_as_ushort(sB[cur][kb + 2 * c + 1][n]) << 16);
                    B2[j][1] = (uint32_t)__half_as_ushort(sB[cur][kb + 2 * c + 8][n])
                             | ((uint32_t)__half_as_ushort(sB[cur][kb + 2 * c + 9][n]) << 16);
                }
                #pragma unroll
                for (int i = 0; i < 4; i++)
                    #pragma unroll
                    for (int j = 0; j < 4; j++)
                        mma_f16(acc[i][j], A4[i], B2[j]);
            }
            __syncthreads();
        }
    }
#undef CLOAD
    __half* crp = g_crph[ks];
    #pragma unroll
    for (int i = 0; i < 4; i++)
        #pragma unroll
        for (int j = 0; j < 4; j++) {
            int r = m0 + i * 16 + g;
            int e = e0 + n0 + j * 8 + 2 * c;
            *(__half2*)&crp[((size_t)(b * R_ + r)) * D_ + e] = __floats2half2_rn(acc[i][j][0], acc[i][j][1]);
            *(__half2*)&crp[((size_t)(b * R_ + r + 8)) * D_ + e] = __floats2half2_rn(acc[i][j][2], acc[i][j][3]);
        }
}

// ---------------- K6: ctx per head (FFMA k-split; A = sum of half split-K partials) ----------------
__global__ void k_ctx(const float* __restrict__ w) {
    const int h = blockIdx.x;
    const int ks = blockIdx.y;
    const int tid = threadIdx.x;
    __shared__ float As[8][132];
    __shared__ float Bs[8][68];
    float acc[8][4];
    #pragma unroll
    for (int i = 0; i < 8; i++) for (int j = 0; j < 4; j++) acc[i][j] = 0.f;
    const int lm = tid >> 1;
    const int lq = (tid & 1) * 4;
    const int ln_ = tid >> 2;
    const int lq2 = (tid & 3) * 2;
    const int ty = tid >> 4;
    const int tx = tid & 15;
    const int bA = lm >> 3, pA = lm & 7;
    const size_t arow = ((size_t)(bA * R_ + h * P_ + pA)) * D_;
    const size_t wrow = (size_t)(2 * D_ + h * HD_ + ln_) * D_;
    for (int k0 = ks * 128; k0 < ks * 128 + 128; k0 += 8) {
        __half2 h0a = *(const __half2*)&g_crph[0][arow + k0 + lq];
        __half2 h0b = *(const __half2*)&g_crph[0][arow + k0 + lq + 2];
        __half2 h1a = *(const __half2*)&g_crph[1][arow + k0 + lq];
        __half2 h1b = *(const __half2*)&g_crph[1][arow + k0 + lq + 2];
        float2 f0a = __half22float2(h0a), f0b = __half22float2(h0b);
        float2 f1a = __half22float2(h1a), f1b = __half22float2(h1b);
        float2 wv = *(const float2*)&w[wrow + k0 + lq2];
        __syncthreads();
        As[lq + 0][lm] = f0a.x + f1a.x; As[lq + 1][lm] = f0a.y + f1a.y;
        As[lq + 2][lm] = f0b.x + f1b.x; As[lq + 3][lm] = f0b.y + f1b.y;
        Bs[lq2 + 0][ln_] = wv.x; Bs[lq2 + 1][ln_] = wv.y;
        __syncthreads();
        #pragma unroll
        for (int kk = 0; kk < 8; kk++) {
            float a[8], bb[4];
            #pragma unroll
            for (int i = 0; i < 8; i++) a[i] = As[kk][ty * 8 + i];
            #pragma unroll
            for (int j = 0; j < 4; j++) bb[j] = Bs[kk][tx * 4 + j];
            #pragma unroll
            for (int i = 0; i < 8; i++)
                #pragma unroll
                for (int j = 0; j < 4; j++) acc[i][j] = fmaf(a[i], bb[j], acc[i][j]);
        }
    }
    #pragma unroll
    for (int i = 0; i < 8; i++) {
        int m = ty * 8 + i;
        *(float4*)&g_ctxp[ks][(size_t)m * D_ + h * HD_ + tx * 4] =
            make_float4(acc[i][0], acc[i][1], acc[i][2], acc[i][3]);
    }
}

// ---------------- K6b: reduce partials + bias -> half ctx ----------------
__global__ void k_ctxred(const float* __restrict__ ipb) {
    int idx = blockIdx.x * 256 + threadIdx.x;
    float s = ipb[2 * D_ + (idx & 1023)];
    #pragma unroll
    for (int ks = 0; ks < 8; ks++) s += g_ctxp[ks][idx];
    g_ctxh[idx] = __float2half_rn(s);
}

// ---------------- K7: pooled = ctx @ out_w^T + ob  (fp16 mma core) ----------------
__global__ void __launch_bounds__(256, 2) k_pool_h(const float* __restrict__ ob) {
    __shared__ __half sA[2][128][40];
    __shared__ __half sB[2][128][40];
    const int f0 = blockIdx.x * 128;
    float acc[4][4][4];
    #pragma unroll
    for (int i = 0; i < 4; i++) for (int j = 0; j < 4; j++) for (int k = 0; k < 4; k++) acc[i][j][k] = 0.f;
    core_h(g_ctxh, g_owh + (size_t)f0 * D_, 32, sA, sB, acc);
    const int lane = threadIdx.x & 31, wid = threadIdx.x >> 5;
    const int g = lane >> 2, c = lane & 3;
    const int m0 = (wid >> 2) * 64, n0 = (wid & 3) * 32;
    #pragma unroll
    for (int i = 0; i < 4; i++)
        #pragma unroll
        for (int j = 0; j < 4; j++) {
            int m = m0 + i * 16 + g;
            int f = f0 + n0 + j * 8 + 2 * c;
            float b0 = ob[f], b1 = ob[f + 1];
            *(float2*)&g_pool[(size_t)m * D_ + f] = make_float2(acc[i][j][0] + b0, acc[i][j][1] + b1);
            *(float2*)&g_pool[(size_t)(m + 8) * D_ + f] = make_float2(acc[i][j][2] + b0, acc[i][j][3] + b1);
        }
}

// ---------------- K8: summary rows + LayerNorms -> half lnv/lng + mask ----------------
__global__ void k_sum(const float* __restrict__ hid,
                      const float* __restrict__ qry,
                      const float* __restrict__ pg, const float* __restrict__ pb,
                      const float* __restrict__ vg, const float* __restrict__ vb,
                      const float* __restrict__ gg, const float* __restrict__ gb) {
    __shared__ float sh[8];
    const int row = blockIdx.x;
    const int tid = threadIdx.x;
    const int j = tid * 4;
    if (row >= NROW) {
        __half2* pv = (__half2*)&g_lnvh[(size_t)row * D_ + j];
        __half2* pgp = (__half2*)&g_lngh[(size_t)row * D_ + j];
        __half2 z = __floats2half2_rn(0.f, 0.f);
        pv[0] = z; pv[1] = z; pgp[0] = z; pgp[1] = z;
        if (tid == 0) g_msk[row] = 0.f;
        return;
    }
    const int b = row / 73, t = row % 73;
    const int len = g_len[b];
    float x[4] = {0.f, 0.f, 0.f, 0.f};
    float msk = 0.f;
    bool ln1 = false;
    if (t == 0) {
        float4 v = *(const float4*)&hid[(size_t)b * S_ * D_ + j];
        x[0] = v.x; x[1] = v.y; x[2] = v.z; x[3] = v.w;
        msk = 1.f;
    } else if (t < 9) {
        int p = t - 1;
        float4 qv = *(const float4*)&qry[(size_t)p * D_ + j];
        float4 pv = *(const float4*)&g_pool[(size_t)(b * P_ + p) * D_ + j];
        x[0] = qv.x + pv.x; x[1] = qv.y + pv.y; x[2] = qv.z + pv.z; x[3] = qv.w + pv.w;
        ln1 = true;
        msk = 1.f;
    } else {
        int s = len - 64 + (t - 9);
        if (s >= 1) {
            float4 v = *(const float4*)&hid[((size_t)b * S_ + s) * D_ + j];
            x[0] = v.x; x[1] = v.y; x[2] = v.z; x[3] = v.w;
            msk = 1.f;
        }
    }
    if (ln1) {
        float sm = blk_red_sum(x[0] + x[1] + x[2] + x[3], sh);
        float mu = sm * (1.f / (float)D_);
        float d0 = x[0] - mu, d1 = x[1] - mu, d2 = x[2] - mu, d3 = x[3] - mu;
        float vq = blk_red_sum(d0 * d0 + d1 * d1 + d2 * d2 + d3 * d3, sh);
        float inv = rsqrtf(vq * (1.f / (float)D_) + 1e-5f);
        #pragma unroll
        for (int c = 0; c < 4; c++) x[c] = (x[c] - mu) * inv * pg[j + c] + pb[j + c];
    }
    float sm = blk_red_sum(x[0] + x[1] + x[2] + x[3], sh);
    float mu = sm * (1.f / (float)D_);
    float d0 = x[0] - mu, d1 = x[1] - mu, d2 = x[2] - mu, d3 = x[3] - mu;
    float vq = blk_red_sum(d0 * d0 + d1 * d1 + d2 * d2 + d3 * d3, sh);
    float inv = rsqrtf(vq * (1.f / (float)D_) + 1e-5f);
    float n0 = (x[0] - mu) * inv, n1 = (x[1] - mu) * inv, n2 = (x[2] - mu) * inv, n3 = (x[3] - mu) * inv;
    __half2* pv = (__half2*)&g_lnvh[(size_t)row * D_ + j];
    __half2* pgp = (__half2*)&g_lngh[(size_t)row * D_ + j];
    pv[0] = __floats2half2_rn(n0 * vg[j] + vb[j], n1 * vg[j + 1] + vb[j + 1]);
    pv[1] = __floats2half2_rn(n2 * vg[j + 2] + vb[j + 2], n3 * vg[j + 3] + vb[j + 3]);
    pgp[0] = __floats2half2_rn(n0 * gg[j] + gb[j], n1 * gg[j + 1] + gb[j + 1]);
    pgp[1] = __floats2half2_rn(n2 * gg[j + 2] + gb[j + 2], n3 * gg[j + 3] + gb[j + 3]);
    if (tid == 0) g_msk[row] = msk;
}

// ---------------- K9: val/gate GEMMs (fp16 mma core) ----------------
__global__ void __launch_bounds__(256, 2) k_vg_h(const float* __restrict__ bvv, const float* __restrict__ bgg) {
    __shared__ __half sA[2][128][40];
    __shared__ __half sB[2][128][40];
    const int which = blockIdx.z;
    const int r0 = blockIdx.x * 128;
    const int f0 = blockIdx.y * 128;
    const __half* Am = which ? g_lngh : g_lnvh;
    const __half* W  = which ? g_wgh : g_wvh;
    const float* bias = which ? bgg : bvv;
    float* out = which ? g_graw : g_vraw;
    float acc[4][4][4];
    #pragma unroll
    for (int i = 0; i < 4; i++) for (int j = 0; j < 4; j++) for (int k = 0; k < 4; k++) acc[i][j][k] = 0.f;
    core_h(Am + (size_t)r0 * D_, W + (size_t)f0 * D_, 32, sA, sB, acc);
    const int lane = threadIdx.x & 31, wid = threadIdx.x >> 5;
    const int g = lane >> 2, c = lane & 3;
    const int m0 = (wid >> 2) * 64, n0 = (wid & 3) * 32;
    #pragma unroll
    for (int i = 0; i < 4; i++)
        #pragma unroll
        for (int j = 0; j < 4; j++) {
            int r = r0 + m0 + i * 16 + g;
            int f = f0 + n0 + j * 8 + 2 * c;
            float b0 = bias[f], b1 = bias[f + 1];
            if (r < NROW)
                *(float2*)&out[(size_t)r * D_ + f] = make_float2(acc[i][j][0] + b0, acc[i][j][1] + b1);
            if (r + 8 < NROW)
                *(float2*)&out[(size_t)(r + 8) * D_ + f] = make_float2(acc[i][j][2] + b0, acc[i][j][3] + b1);
        }
}

// ---------------- K10: gated = silu(vraw)*sigmoid(graw)*mask -> output ----------------
__global__ void k_out(float* __restrict__ out, int write_mask) {
    int idx = blockIdx.x * 256 + threadIdx.x;
    if (idx < NROW * D_) {
        int row = idx >> 10;
        float v = g_vraw[idx], g = g_graw[idx];
        float sv = v / (1.f + __expf(-v));
        float sg = 1.f / (1.f + __expf(-g));
        out[idx] = sv * sg * g_msk[row];
    }
    if (write_mask && idx < NROW) {
        out[NROW * D_ + idx] = g_msk[idx];
    }
}

// ---------------- host launcher ----------------
extern "C" void kernel_launch(void* const* d_in, const int* in_sizes, int n_in,
                              void* d_out, int out_size) {
    (void)in_sizes; (void)n_in;
    const float* hid = (const float*)d_in[0];
    const void*  vm  = d_in[1];
    const float* qry = (const float*)d_in[2];
    const float* ipw = (const float*)d_in[3];
    const float* ipb = (const float*)d_in[4];
    const float* ow  = (const float*)d_in[5];
    const float* ob  = (const float*)d_in[6];
    const float* pg  = (const float*)d_in[7];
    const float* pb  = (const float*)d_in[8];
    const float* vg  = (const float*)d_in[9];
    const float* vb  = (const float*)d_in[10];
    const float* Wv  = (const float*)d_in[11];
    const float* bv  = (const float*)d_in[12];
    const float* gg  = (const float*)d_in[13];
    const float* gb  = (const float*)d_in[14];
    const float* Wg  = (const float*)d_in[15];
    const float* bg  = (const float*)d_in[16];
    float* out = (float*)d_out;

    // Forked-stream prep phase, R13 arrangement (known-good).
    cudaStream_t s1 = 0, s2 = 0;
    cudaEvent_t evRoot = 0, evA = 0, evW = 0;
    bool forked =
        cudaStreamCreateWithFlags(&s1, cudaStreamNonBlocking) == cudaSuccess &&
        cudaStreamCreateWithFlags(&s2, cudaStreamNonBlocking) == cudaSuccess &&
        cudaEventCreateWithFlags(&evRoot, cudaEventDisableTiming) == cudaSuccess &&
        cudaEventCreateWithFlags(&evA, cudaEventDisableTiming) == cudaSuccess &&
        cudaEventCreateWithFlags(&evW, cudaEventDisableTiming) == cudaSuccess;

    if (forked) {
        cudaEventRecord(evRoot, 0);
        cudaStreamWaitEvent(s1, evRoot, 0);
        cudaStreamWaitEvent(s2, evRoot, 0);
        k_q<<<1024, 256, 0, s1>>>(qry, ipw, ipb);
        k_A<<<512, 256, 0, s1>>>(ipw);
        cudaEventRecord(evA, s1);
        k_cvtW<<<512, 256, 0, s2>>>(Wv, Wg, ow);
        cudaEventRecord(evW, s2);
        k_lentiles<<<1, 256>>>(vm);
        k_cvthid<<<dim3(512, 16), 256>>>(hid);
        cudaStreamWaitEvent(0, evA, 0);
        cudaStreamWaitEvent(0, evW, 0);
    } else {
        k_lentiles<<<1, 256>>>(vm);
        k_q<<<1024, 256>>>(qry, ipw, ipb);
        k_A<<<512, 256>>>(ipw);
        k_cvtW<<<512, 256>>>(Wv, Wg, ow);
        k_cvthid<<<dim3(512, 16), 256>>>(hid);
    }

    k_scores_h<<<256, 256>>>();
    k_softmax<<<B_ * R_, 256>>>();
    k_ctxraw_h<<<dim3(8, 16, 2), 256>>>();
    k_ctx<<<dim3(16, 8), 256>>>(ipw);
    k_ctxred<<<512, 256>>>(ipb);
    k_pool_h<<<8, 256>>>(ob);
    k_sum<<<NROWP, 256>>>(hid, qry, pg, pb, vg, vb, gg, gb);
    k_vg_h<<<dim3(10, 8, 2), 256>>>(bv, bg);
    int wm = (out_size >= NROW * D_ + NROW) ? 1 : 0;
    k_out<<<(NROW * D_ + 255) / 256, 256>>>(out, wm);

    if (s1) cudaStreamDestroy(s1);
    if (s2) cudaStreamDestroy(s2);
    if (evRoot) cudaEventDestroy(evRoot);
    if (evA) cudaEventDestroy(evA);
    if (evW) cudaEventDestroy(evW);
}

// round 16
// speedup vs baseline: 1.0652x; 1.0515x over previous
#include <cuda_runtime.h>
#include <cuda_fp16.h>
#include <math.h>
#include <stdint.h>

#define B_    16
#define S_    2048
#define D_    1024
#define H_    16
#define P_    8
#define R_    128      // H_*P_
#define HD_   64
#define SUMN  73
#define NROW  1168     // B_*SUMN
#define NROWP 1280     // padded to 10*128

// ---------------- scratch (static device globals; no allocation) ----------------
__device__ int    g_len[B_];
__device__ int    g_tcnt;
__device__ int    g_tiles[B_ * 16];
__device__ float  g_q[P_ * D_];
__device__ __half g_Ah[R_ * D_];
__device__ __half g_hidh[(size_t)B_ * S_ * D_];   // zero-init; only rows s<len written
__device__ __half g_sch[(size_t)B_ * R_ * S_];    // half scores -> attn (in place)
__device__ __half g_crph[2][(size_t)B_ * R_ * D_]; // ctxRaw split-K partials (half)
__device__ float  g_ctxp[8][R_ * D_];
__device__ __half g_ctxh[R_ * D_];
__device__ float  g_poolp2[2][R_ * D_];           // pool split-K partials (no bias)
__device__ __half g_lnvh[(size_t)NROWP * D_];
__device__ __half g_lngh[(size_t)NROWP * D_];
__device__ __half g_wvh[D_ * D_];
__device__ __half g_wgh[D_ * D_];
__device__ __half g_owh[D_ * D_];
__device__ float  g_vraw[(size_t)NROW * D_];
__device__ float  g_graw[(size_t)NROW * D_];
__device__ float  g_msk[NROWP];

// ---------------- helpers ----------------
__device__ __forceinline__ uint32_t su(const void* p) {
    return (uint32_t)__cvta_generic_to_shared(p);
}
__device__ __forceinline__ void cpa16(uint32_t dst, const void* src) {
    asm volatile("cp.async.cg.shared.global [%0], [%1], 16;" :: "r"(dst), "l"(src));
}
#define CP_COMMIT() asm volatile("cp.async.commit_group;")
#define CP_WAIT1()  asm volatile("cp.async.wait_group 1;")

__device__ __forceinline__ void mma_f16(float* d, const uint32_t* a, const uint32_t* b) {
    asm volatile(
        "mma.sync.aligned.m16n8k16.row.col.f32.f16.f16.f32 "
        "{%0,%1,%2,%3}, {%4,%5,%6,%7}, {%8,%9}, {%0,%1,%2,%3};"
        : "+f"(d[0]), "+f"(d[1]), "+f"(d[2]), "+f"(d[3])
        : "r"(a[0]), "r"(a[1]), "r"(a[2]), "r"(a[3]), "r"(b[0]), "r"(b[1]));
}

__device__ __forceinline__ float blk_red_sum(float v, float* sh) {
    #pragma unroll
    for (int o = 16; o > 0; o >>= 1) v += __shfl_down_sync(0xffffffffu, v, o);
    int w = threadIdx.x >> 5, l = threadIdx.x & 31;
    __syncthreads();
    if (l == 0) sh[w] = v;
    __syncthreads();
    float r = 0.f;
    #pragma unroll
    for (int i = 0; i < 8; i++) r += sh[i];
    return r;
}
__device__ __forceinline__ float blk_red_max(float v, float* sh) {
    #pragma unroll
    for (int o = 16; o > 0; o >>= 1) v = fmaxf(v, __shfl_down_sync(0xffffffffu, v, o));
    int w = threadIdx.x >> 5, l = threadIdx.x & 31;
    __syncthreads();
    if (l == 0) sh[w] = v;
    __syncthreads();
    float r = -3.4e38f;
    #pragma unroll
    for (int i = 0; i < 8; i++) r = fmaxf(r, sh[i]);
    return r;
}

// ---------------- fp16 mma core: C[128x128] = A[128xK] . B[128xK]^T ----------------
// 256 threads, 8 warps, 64x32 warp tiles. Both operands K-major half, row stride D_.
__device__ __forceinline__ void core_h(
    const __half* __restrict__ Ar, const __half* __restrict__ Br, int NT32,
    __half sA[2][128][40], __half sB[2][128][40], float acc[4][4][4])
{
    const int tid = threadIdx.x;
    const int wid = tid >> 5, lane = tid & 31;
    const int g = lane >> 2, c = lane & 3;
    const int m0 = (wid >> 2) * 64, n0 = (wid & 3) * 32;

#define HLOAD(T, BUF) { \
    int kg = (T) * 32; \
    _Pragma("unroll") \
    for (int q = 0; q < 2; q++) { \
        int idx = tid + q * 256; \
        int row = idx >> 2, cc = idx & 3; \
        cpa16(su(&sA[BUF][row][cc * 8]), Ar + (size_t)row * D_ + kg + cc * 8); \
        cpa16(su(&sB[BUF][row][cc * 8]), Br + (size_t)row * D_ + kg + cc * 8); \
    } }

    HLOAD(0, 0); CP_COMMIT();
    for (int t = 0; t < NT32; t++) {
        int cur = t & 1;
        if (t + 1 < NT32) { HLOAD(t + 1, cur ^ 1); }
        CP_COMMIT(); CP_WAIT1(); __syncthreads();
        #pragma unroll
        for (int sub = 0; sub < 2; sub++) {
            int kb = sub * 16;
            uint32_t A4[4][4], B2[4][2];
            #pragma unroll
            for (int i = 0; i < 4; i++) {
                A4[i][0] = *(const uint32_t*)&sA[cur][m0 + i * 16 + g][kb + 2 * c];
                A4[i][1] = *(const uint32_t*)&sA[cur][m0 + i * 16 + g + 8][kb + 2 * c];
                A4[i][2] = *(const uint32_t*)&sA[cur][m0 + i * 16 + g][kb + 2 * c + 8];
                A4[i][3] = *(const uint32_t*)&sA[cur][m0 + i * 16 + g + 8][kb + 2 * c + 8];
            }
            #pragma unroll
            for (int j = 0; j < 4; j++) {
                B2[j][0] = *(const uint32_t*)&sB[cur][n0 + j * 8 + g][kb + 2 * c];
                B2[j][1] = *(const uint32_t*)&sB[cur][n0 + j * 8 + g][kb + 2 * c + 8];
            }
            #pragma unroll
            for (int i = 0; i < 4; i++)
                #pragma unroll
                for (int j = 0; j < 4; j++)
                    mma_f16(acc[i][j], A4[i], B2[j]);
        }
        __syncthreads();
    }
#undef HLOAD
}

// ---------------- K0: lengths via ballot-parallel prefix search + tile list; ONE block ----------------
__global__ void k_lentiles(const void* __restrict__ vmraw) {
    __shared__ int is_u8;
    const unsigned char* vb = (const unsigned char*)vmraw;
    const int* vi = (const int*)vmraw;
    const int tid = threadIdx.x, wid = tid >> 5, lane = tid & 31;
    if (tid == 0) {
        int ones = 0;
        #pragma unroll
        for (int i = 0; i < 16; i++) ones += (vb[i] != 0) ? 1 : 0;
        is_u8 = (ones > 4) ? 1 : 0;
    }
    __syncthreads();
    const int u8 = is_u8;
    #pragma unroll
    for (int pass = 0; pass < 2; pass++) {
        const int b = wid + pass * 8;
        const size_t boff = (size_t)b * S_;
        int p1 = lane * 64;
        int v1 = u8 ? (vb[boff + p1] != 0) : (vi[boff + p1] != 0);
        unsigned m1 = __ballot_sync(0xffffffffu, v1);
        int base = (31 - __clz(m1)) * 64;
        int p2 = base + lane * 2;
        int v2 = u8 ? (vb[boff + p2] != 0) : (vi[boff + p2] != 0);
        unsigned m2 = __ballot_sync(0xffffffffu, v2);
        base += (31 - __clz(m2)) * 2;
        int v3 = u8 ? (vb[boff + base + 1] != 0) : (vi[boff + base + 1] != 0);
        if (lane == 0) g_len[b] = base + 1 + (v3 ? 1 : 0);
    }
    __syncthreads();
    if (tid == 0) {
        int cnt = 0;
        for (int t = 0; t < 16; t++)
            for (int bb = 0; bb < B_; bb++)
                if (t * 128 < g_len[bb]) g_tiles[cnt++] = (bb << 4) | t;
        g_tcnt = cnt;
    }
}

// ---------------- K1: q = queries @ Wq^T + bq ----------------
__global__ void k_q(const float* __restrict__ qry, const float* __restrict__ w,
                    const float* __restrict__ bia) {
    int wid = (blockIdx.x * 256 + threadIdx.x) >> 5;
    int l = threadIdx.x & 31;
    int p = wid >> 10;
    int j = wid & 1023;
    const float* qr = qry + (size_t)p * D_;
    const float* wr = w + (size_t)j * D_;
    float s = 0.f;
    for (int e = l; e < D_; e += 32) s += qr[e] * wr[e];
    #pragma unroll
    for (int o = 16; o > 0; o >>= 1) s += __shfl_down_sync(0xffffffffu, s, o);
    if (l == 0) g_q[p * D_ + j] = s + bia[j];
}

// ---------------- K2: A[r][e] = (1/8) * sum_d q[p][h*64+d] * Wk[h*64+d][e] -> half ----------------
__global__ void k_A(const float* __restrict__ w) {
    int idx = blockIdx.x * 256 + threadIdx.x;
    int r = idx >> 10, e = idx & 1023;
    int h = r >> 3, p = r & 7;
    const float* qrow = g_q + p * D_ + h * HD_;
    const float* wr = w + (size_t)(D_ + h * HD_) * D_ + e;
    float s = 0.f;
    #pragma unroll 8
    for (int d = 0; d < HD_; d++) s += qrow[d] * wr[(size_t)d * D_];
    g_Ah[idx] = __float2half_rn(0.125f * s);
}

// ---------------- K2b: convert W_v / W_g / out_w to half (8 elems/thread) ----------------
__global__ void k_cvtW(const float* __restrict__ wv, const float* __restrict__ wg,
                       const float* __restrict__ ow) {
    int i = (blockIdx.x * 256 + threadIdx.x) * 8;
    #pragma unroll
    for (int u = 0; u < 2; u++) {
        float4 a = *(const float4*)(wv + i + u * 4);
        float4 b = *(const float4*)(wg + i + u * 4);
        float4 o = *(const float4*)(ow + i + u * 4);
        __half2* dv = (__half2*)(g_wvh + i + u * 4);
        __half2* dg = (__half2*)(g_wgh + i + u * 4);
        __half2* doo = (__half2*)(g_owh + i + u * 4);
        dv[0] = __floats2half2_rn(a.x, a.y); dv[1] = __floats2half2_rn(a.z, a.w);
        dg[0] = __floats2half2_rn(b.x, b.y); dg[1] = __floats2half2_rn(b.z, b.w);
        doo[0] = __floats2half2_rn(o.x, o.y); doo[1] = __floats2half2_rn(o.z, o.w);
    }
}

// ---------------- K2c: convert hidden to half, ONLY rows s < len[b] (4 rows/block) ----------------
__global__ void k_cvthid(const float* __restrict__ hid) {
    const int b = blockIdx.y;
    const int s0 = blockIdx.x * 4;
    if (s0 >= g_len[b]) return;
    size_t base = ((size_t)b * S_ + s0) * D_;
    #pragma unroll
    for (int u = 0; u < 2; u++) {
        size_t i = base + threadIdx.x * 8 + (size_t)u * 2048;
        float4 a = *(const float4*)(hid + i);
        float4 c = *(const float4*)(hid + i + 4);
        __half2* dst = (__half2*)(g_hidh + i);
        dst[0] = __floats2half2_rn(a.x, a.y);
        dst[1] = __floats2half2_rn(a.z, a.w);
        dst[2] = __floats2half2_rn(c.x, c.y);
        dst[3] = __floats2half2_rn(c.z, c.w);
    }
}

// ---------------- K3: scores = A . hidden^T  (fp16 mma; writes HALF scores) ----------------
__global__ void __launch_bounds__(256, 2) k_scores_h() {
    __shared__ __half sA[2][128][40];
    __shared__ __half sB[2][128][40];
    if (blockIdx.x >= g_tcnt) return;
    const int tile = g_tiles[blockIdx.x];
    const int b = tile >> 4;
    const int s0 = (tile & 15) * 128;
    float acc[4][4][4];
    #pragma unroll
    for (int i = 0; i < 4; i++) for (int j = 0; j < 4; j++) for (int k = 0; k < 4; k++) acc[i][j][k] = 0.f;
    core_h(g_Ah, g_hidh + ((size_t)b * S_ + s0) * D_, 32, sA, sB, acc);
    const int lane = threadIdx.x & 31, wid = threadIdx.x >> 5;
    const int g = lane >> 2, c = lane & 3;
    const int m0 = (wid >> 2) * 64, n0 = (wid & 3) * 32;
    #pragma unroll
    for (int i = 0; i < 4; i++)
        #pragma unroll
        for (int j = 0; j < 4; j++) {
            int r = m0 + i * 16 + g;
            int s = s0 + n0 + j * 8 + 2 * c;
            *(__half2*)&g_sch[((size_t)(b * R_ + r)) * S_ + s] = __floats2half2_rn(acc[i][j][0], acc[i][j][1]);
            *(__half2*)&g_sch[((size_t)(b * R_ + r + 8)) * S_ + s] = __floats2half2_rn(acc[i][j][2], acc[i][j][3]);
        }
}

// ---------------- K4: softmax over s<len (half in, half out, in place); zero-fills to 128 ----------------
__global__ void k_softmax() {
    __shared__ float sh[8];
    int row = blockIdx.x;
    int b = row >> 7;
    int len = g_len[b];
    size_t base = (size_t)row * S_;
    int tid = threadIdx.x;
    float v[8];
    int n = 0;
    float mx = -3.4e38f;
    for (int i = tid; i < len; i += 256) { float x = __half2float(g_sch[base + i]); v[n++] = x; mx = fmaxf(mx, x); }
    float bm = blk_red_max(mx, sh);
    float s = 0.f;
    for (int k = 0; k < n; k++) { v[k] = __expf(v[k] - bm); s += v[k]; }
    float bs = blk_red_sum(s, sh);
    float inv = 1.f / bs;
    n = 0;
    for (int i = tid; i < len; i += 256) g_sch[base + i] = __float2half_rn(v[n++] * inv);
    int rend = (len + 127) & ~127;
    for (int i = len + tid; i < rend; i += 256) g_sch[base + i] = __ushort_as_half((unsigned short)0);
}

// ---------------- K5: ctxRaw = attn . hidden  (fp16 mma; B MN-major; split-K x2; half partials) ----------------
__global__ void __launch_bounds__(256, 2) k_ctxraw_h() {
    __shared__ __half sA[2][128][40];
    __shared__ __half sB[2][32][136];
    const int b = blockIdx.y;
    const int e0 = blockIdx.x * 128;
    const int ks = blockIdx.z;
    const int len = g_len[b];
    const int NT32 = (len + 31) >> 5;
    const int t0 = ks * 32;
    const int t1 = (NT32 < t0 + 32) ? NT32 : (t0 + 32);
    const int tid = threadIdx.x;
    const int wid = tid >> 5, lane = tid & 31;
    const int g = lane >> 2, c = lane & 3;
    const int m0 = (wid >> 2) * 64, n0 = (wid & 3) * 32;
    const __half* hb = g_hidh + (size_t)b * S_ * D_;
    const __half* ab = g_sch + ((size_t)b * R_) * S_;
    float acc[4][4][4];
    #pragma unroll
    for (int i = 0; i < 4; i++) for (int j = 0; j < 4; j++) for (int k = 0; k < 4; k++) acc[i][j][k] = 0.f;

#define CLOAD(T, BUF) { \
    int kg = (T) * 32; \
    _Pragma("unroll") \
    for (int q = 0; q < 2; q++) { \
        int idx = tid + q * 256; \
        int ar = idx >> 2, ac = idx & 3; \
        cpa16(su(&sA[BUF][ar][ac * 8]), ab + (size_t)ar * S_ + kg + ac * 8); \
        int br = idx >> 4, bc = idx & 15; \
        cpa16(su(&sB[BUF][br][bc * 8]), hb + (size_t)(kg + br) * D_ + e0 + bc * 8); \
    } }

    if (t0 < t1) {
        CLOAD(t0, 0); CP_COMMIT();
        for (int t = t0; t < t1; t++) {
            int cur = (t - t0) & 1;
            if (t + 1 < t1) { CLOAD(t + 1, cur ^ 1); }
            CP_COMMIT(); CP_WAIT1(); __syncthreads();
            #pragma unroll
            for (int sub = 0; sub < 2; sub++) {
                int kb = sub * 16;
                uint32_t A4[4][4], B2[4][2];
                #pragma unroll
                for (int i = 0; i < 4; i++) {
                    A4[i][0] = *(const uint32_t*)&sA[cur][m0 + i * 16 + g][kb + 2 * c];
                    A4[i][1] = *(const uint32_t*)&sA[cur][m0 + i * 16 + g + 8][kb + 2 * c];
                    A4[i][2] = *(const uint32_t*)&sA[cur][m0 + i * 16 + g][kb + 2 * c + 8];
                    A4[i][3] = *(const uint32_t*)&sA[cur][m0 + i * 16 + g + 8][kb + 2 * c + 8];
                }
                #pragma unroll
                for (int j = 0; j < 4; j++) {
                    int n = n0 + j * 8 + g;
                    B2[j][0] = (uint32_t)__half_as_ushort(sB[cur][kb + 2 * c][n])
                             | ((uint32_t)__half_as_ushort(sB[cur][kb + 2 * c + 1][n]) << 16);
                    B2[j][1] = (uint32_t)__half_as_ushort(sB[cur][kb + 2 * c + 8][n])
                             | ((uint32_t)__half_as_ushort(sB[cur][kb + 2 * c + 9][n]) << 16);
                }
                #pragma unroll
                for (int i = 0; i < 4; i++)
                    #pragma unroll
                    for (int j = 0; j < 4; j++)
                        mma_f16(acc[i][j], A4[i], B2[j]);
            }
            __syncthreads();
        }
    }
#undef CLOAD
    __half* crp = g_crph[ks];
    #pragma unroll
    for (int i = 0; i < 4; i++)
        #pragma unroll
        for (int j = 0; j < 4; j++) {
            int r = m0 + i * 16 + g;
            int e = e0 + n0 + j * 8 + 2 * c;
            *(__half2*)&crp[((size_t)(b * R_ + r)) * D_ + e] = __floats2half2_rn(acc[i][j][0], acc[i][j][1]);
            *(__half2*)&crp[((size_t)(b * R_ + r + 8)) * D_ + e] = __floats2half2_rn(acc[i][j][2], acc[i][j][3]);
        }
}

// ---------------- K6: ctx per head (FFMA k-split; A = sum of half split-K partials) ----------------
__global__ void k_ctx(const float* __restrict__ w) {
    const int h = blockIdx.x;
    const int ks = blockIdx.y;
    const int tid = threadIdx.x;
    __shared__ float As[8][132];
    __shared__ float Bs[8][68];
    float acc[8][4];
    #pragma unroll
    for (int i = 0; i < 8; i++) for (int j = 0; j < 4; j++) acc[i][j] = 0.f;
    const int lm = tid >> 1;
    const int lq = (tid & 1) * 4;
    const int ln_ = tid >> 2;
    const int lq2 = (tid & 3) * 2;
    const int ty = tid >> 4;
    const int tx = tid & 15;
    const int bA = lm >> 3, pA = lm & 7;
    const size_t arow = ((size_t)(bA * R_ + h * P_ + pA)) * D_;
    const size_t wrow = (size_t)(2 * D_ + h * HD_ + ln_) * D_;
    for (int k0 = ks * 128; k0 < ks * 128 + 128; k0 += 8) {
        __half2 h0a = *(const __half2*)&g_crph[0][arow + k0 + lq];
        __half2 h0b = *(const __half2*)&g_crph[0][arow + k0 + lq + 2];
        __half2 h1a = *(const __half2*)&g_crph[1][arow + k0 + lq];
        __half2 h1b = *(const __half2*)&g_crph[1][arow + k0 + lq + 2];
        float2 f0a = __half22float2(h0a), f0b = __half22float2(h0b);
        float2 f1a = __half22float2(h1a), f1b = __half22float2(h1b);
        float2 wv = *(const float2*)&w[wrow + k0 + lq2];
        __syncthreads();
        As[lq + 0][lm] = f0a.x + f1a.x; As[lq + 1][lm] = f0a.y + f1a.y;
        As[lq + 2][lm] = f0b.x + f1b.x; As[lq + 3][lm] = f0b.y + f1b.y;
        Bs[lq2 + 0][ln_] = wv.x; Bs[lq2 + 1][ln_] = wv.y;
        __syncthreads();
        #pragma unroll
        for (int kk = 0; kk < 8; kk++) {
            float a[8], bb[4];
            #pragma unroll
            for (int i = 0; i < 8; i++) a[i] = As[kk][ty * 8 + i];
            #pragma unroll
            for (int j = 0; j < 4; j++) bb[j] = Bs[kk][tx * 4 + j];
            #pragma unroll
            for (int i = 0; i < 8; i++)
                #pragma unroll
                for (int j = 0; j < 4; j++) acc[i][j] = fmaf(a[i], bb[j], acc[i][j]);
        }
    }
    #pragma unroll
    for (int i = 0; i < 8; i++) {
        int m = ty * 8 + i;
        *(float4*)&g_ctxp[ks][(size_t)m * D_ + h * HD_ + tx * 4] =
            make_float4(acc[i][0], acc[i][1], acc[i][2], acc[i][3]);
    }
}

// ---------------- K6b: reduce partials + bias -> half ctx ----------------
__global__ void k_ctxred(const float* __restrict__ ipb) {
    int idx = blockIdx.x * 256 + threadIdx.x;
    float s = ipb[2 * D_ + (idx & 1023)];
    #pragma unroll
    for (int ks = 0; ks < 8; ks++) s += g_ctxp[ks][idx];
    g_ctxh[idx] = __float2half_rn(s);
}

// ---------------- K7: pooled partials = ctx @ out_w^T  (fp16 mma; split-K x2; no bias) ----------------
__global__ void __launch_bounds__(256, 2) k_pool_h() {
    __shared__ __half sA[2][128][40];
    __shared__ __half sB[2][128][40];
    const int f0 = blockIdx.x * 128;
    const int z = blockIdx.y;
    float acc[4][4][4];
    #pragma unroll
    for (int i = 0; i < 4; i++) for (int j = 0; j < 4; j++) for (int k = 0; k < 4; k++) acc[i][j][k] = 0.f;
    core_h(g_ctxh + z * 512, g_owh + (size_t)f0 * D_ + z * 512, 16, sA, sB, acc);
    const int lane = threadIdx.x & 31, wid = threadIdx.x >> 5;
    const int g = lane >> 2, c = lane & 3;
    const int m0 = (wid >> 2) * 64, n0 = (wid & 3) * 32;
    float* dst = g_poolp2[z];
    #pragma unroll
    for (int i = 0; i < 4; i++)
        #pragma unroll
        for (int j = 0; j < 4; j++) {
            int m = m0 + i * 16 + g;
            int f = f0 + n0 + j * 8 + 2 * c;
            *(float2*)&dst[(size_t)m * D_ + f] = make_float2(acc[i][j][0], acc[i][j][1]);
            *(float2*)&dst[(size_t)(m + 8) * D_ + f] = make_float2(acc[i][j][2], acc[i][j][3]);
        }
}

// ---------------- K8: summary rows + LayerNorms -> half lnv/lng + mask ----------------
__global__ void k_sum(const float* __restrict__ hid,
                      const float* __restrict__ qry, const float* __restrict__ ob,
                      const float* __restrict__ pg, const float* __restrict__ pb,
                      const float* __restrict__ vg, const float* __restrict__ vb,
                      const float* __restrict__ gg, const float* __restrict__ gb) {
    __shared__ float sh[8];
    const int row = blockIdx.x;
    const int tid = threadIdx.x;
    const int j = tid * 4;
    if (row >= NROW) {
        __half2* pv = (__half2*)&g_lnvh[(size_t)row * D_ + j];
        __half2* pgp = (__half2*)&g_lngh[(size_t)row * D_ + j];
        __half2 z = __floats2half2_rn(0.f, 0.f);
        pv[0] = z; pv[1] = z; pgp[0] = z; pgp[1] = z;
        if (tid == 0) g_msk[row] = 0.f;
        return;
    }
    const int b = row / 73, t = row % 73;
    const int len = g_len[b];
    float x[4] = {0.f, 0.f, 0.f, 0.f};
    float msk = 0.f;
    bool ln1 = false;
    if (t == 0) {
        float4 v = *(const float4*)&hid[(size_t)b * S_ * D_ + j];
        x[0] = v.x; x[1] = v.y; x[2] = v.z; x[3] = v.w;
        msk = 1.f;
    } else if (t < 9) {
        int p = t - 1;
        float4 qv = *(const float4*)&qry[(size_t)p * D_ + j];
        float4 p0 = *(const float4*)&g_poolp2[0][(size_t)(b * P_ + p) * D_ + j];
        float4 p1 = *(const float4*)&g_poolp2[1][(size_t)(b * P_ + p) * D_ + j];
        float4 o4 = *(const float4*)&ob[j];
        x[0] = qv.x + p0.x + p1.x + o4.x;
        x[1] = qv.y + p0.y + p1.y + o4.y;
        x[2] = qv.z + p0.z + p1.z + o4.z;
        x[3] = qv.w + p0.w + p1.w + o4.w;
        ln1 = true;
        msk = 1.f;
    } else {
        int s = len - 64 + (t - 9);
        if (s >= 1) {
            float4 v = *(const float4*)&hid[((size_t)b * S_ + s) * D_ + j];
            x[0] = v.x; x[1] = v.y; x[2] = v.z; x[3] = v.w;
            msk = 1.f;
        }
    }
    if (ln1) {
        float sm = blk_red_sum(x[0] + x[1] + x[2] + x[3], sh);
        float mu = sm * (1.f / (float)D_);
        float d0 = x[0] - mu, d1 = x[1] - mu, d2 = x[2] - mu, d3 = x[3] - mu;
        float vq = blk_red_sum(d0 * d0 + d1 * d1 + d2 * d2 + d3 * d3, sh);
        float inv = rsqrtf(vq * (1.f / (float)D_) + 1e-5f);
        #pragma unroll
        for (int c = 0; c < 4; c++) x[c] = (x[c] - mu) * inv * pg[j + c] + pb[j + c];
    }
    float sm = blk_red_sum(x[0] + x[1] + x[2] + x[3], sh);
    float mu = sm * (1.f / (float)D_);
    float d0 = x[0] - mu, d1 = x[1] - mu, d2 = x[2] - mu, d3 = x[3] - mu;
    float vq = blk_red_sum(d0 * d0 + d1 * d1 + d2 * d2 + d3 * d3, sh);
    float inv = rsqrtf(vq * (1.f / (float)D_) + 1e-5f);
    float n0 = (x[0] - mu) * inv, n1 = (x[1] - mu) * inv, n2 = (x[2] - mu) * inv, n3 = (x[3] - mu) * inv;
    __half2* pv = (__half2*)&g_lnvh[(size_t)row * D_ + j];
    __half2* pgp = (__half2*)&g_lngh[(size_t)row * D_ + j];
    pv[0] = __floats2half2_rn(n0 * vg[j] + vb[j], n1 * vg[j + 1] + vb[j + 1]);
    pv[1] = __floats2half2_rn(n2 * vg[j + 2] + vb[j + 2], n3 * vg[j + 3] + vb[j + 3]);
    pgp[0] = __floats2half2_rn(n0 * gg[j] + gb[j], n1 * gg[j + 1] + gb[j + 1]);
    pgp[1] = __floats2half2_rn(n2 * gg[j + 2] + gb[j + 2], n3 * gg[j + 3] + gb[j + 3]);
    if (tid == 0) g_msk[row] = msk;
}

// ---------------- K9: val/gate GEMMs (fp16 mma core) ----------------
__global__ void __launch_bounds__(256, 2) k_vg_h(const float* __restrict__ bvv, const float* __restrict__ bgg) {
    __shared__ __half sA[2][128][40];
    __shared__ __half sB[2][128][40];
    const int which = blockIdx.z;
    const int r0 = blockIdx.x * 128;
    const int f0 = blockIdx.y * 128;
    const __half* Am = which ? g_lngh : g_lnvh;
    const __half* W  = which ? g_wgh : g_wvh;
    const float* bias = which ? bgg : bvv;
    float* out = which ? g_graw : g_vraw;
    float acc[4][4][4];
    #pragma unroll
    for (int i = 0; i < 4; i++) for (int j = 0; j < 4; j++) for (int k = 0; k < 4; k++) acc[i][j][k] = 0.f;
    core_h(Am + (size_t)r0 * D_, W + (size_t)f0 * D_, 32, sA, sB, acc);
    const int lane = threadIdx.x & 31, wid = threadIdx.x >> 5;
    const int g = lane >> 2, c = lane & 3;
    const int m0 = (wid >> 2) * 64, n0 = (wid & 3) * 32;
    #pragma unroll
    for (int i = 0; i < 4; i++)
        #pragma unroll
        for (int j = 0; j < 4; j++) {
            int r = r0 + m0 + i * 16 + g;
            int f = f0 + n0 + j * 8 + 2 * c;
            float b0 = bias[f], b1 = bias[f + 1];
            if (r < NROW)
                *(float2*)&out[(size_t)r * D_ + f] = make_float2(acc[i][j][0] + b0, acc[i][j][1] + b1);
            if (r + 8 < NROW)
                *(float2*)&out[(size_t)(r + 8) * D_ + f] = make_float2(acc[i][j][2] + b0, acc[i][j][3] + b1);
        }
}

// ---------------- K10: gated = silu(vraw)*sigmoid(graw)*mask -> output ----------------
__global__ void k_out(float* __restrict__ out, int write_mask) {
    int idx = blockIdx.x * 256 + threadIdx.x;
    if (idx < NROW * D_) {
        int row = idx >> 10;
        float v = g_vraw[idx], g = g_graw[idx];
        float sv = v / (1.f + __expf(-v));
        float sg = 1.f / (1.f + __expf(-g));
        out[idx] = sv * sg * g_msk[row];
    }
    if (write_mask && idx < NROW) {
        out[NROW * D_ + idx] = g_msk[idx];
    }
}

// ---------------- host launcher ----------------
extern "C" void kernel_launch(void* const* d_in, const int* in_sizes, int n_in,
                              void* d_out, int out_size) {
    (void)in_sizes; (void)n_in;
    const float* hid = (const float*)d_in[0];
    const void*  vm  = d_in[1];
    const float* qry = (const float*)d_in[2];
    const float* ipw = (const float*)d_in[3];
    const float* ipb = (const float*)d_in[4];
    const float* ow  = (const float*)d_in[5];
    const float* ob  = (const float*)d_in[6];
    const float* pg  = (const float*)d_in[7];
    const float* pb  = (const float*)d_in[8];
    const float* vg  = (const float*)d_in[9];
    const float* vb  = (const float*)d_in[10];
    const float* Wv  = (const float*)d_in[11];
    const float* bv  = (const float*)d_in[12];
    const float* gg  = (const float*)d_in[13];
    const float* gb  = (const float*)d_in[14];
    const float* Wg  = (const float*)d_in[15];
    const float* bg  = (const float*)d_in[16];
    float* out = (float*)d_out;

    // Forked-stream prep phase, R13 arrangement (known-good).
    cudaStream_t s1 = 0, s2 = 0;
    cudaEvent_t evRoot = 0, evA = 0, evW = 0;
    bool forked =
        cudaStreamCreateWithFlags(&s1, cudaStreamNonBlocking) == cudaSuccess &&
        cudaStreamCreateWithFlags(&s2, cudaStreamNonBlocking) == cudaSuccess &&
        cudaEventCreateWithFlags(&evRoot, cudaEventDisableTiming) == cudaSuccess &&
        cudaEventCreateWithFlags(&evA, cudaEventDisableTiming) == cudaSuccess &&
        cudaEventCreateWithFlags(&evW, cudaEventDisableTiming) == cudaSuccess;

    if (forked) {
        cudaEventRecord(evRoot, 0);
        cudaStreamWaitEvent(s1, evRoot, 0);
        cudaStreamWaitEvent(s2, evRoot, 0);
        k_q<<<1024, 256, 0, s1>>>(qry, ipw, ipb);
        k_A<<<512, 256, 0, s1>>>(ipw);
        cudaEventRecord(evA, s1);
        k_cvtW<<<512, 256, 0, s2>>>(Wv, Wg, ow);
        cudaEventRecord(evW, s2);
        k_lentiles<<<1, 256>>>(vm);
        k_cvthid<<<dim3(512, 16), 256>>>(hid);
        cudaStreamWaitEvent(0, evA, 0);
        cudaStreamWaitEvent(0, evW, 0);
    } else {
        k_lentiles<<<1, 256>>>(vm);
        k_q<<<1024, 256>>>(qry, ipw, ipb);
        k_A<<<512, 256>>>(ipw);
        k_cvtW<<<512, 256>>>(Wv, Wg, ow);
        k_cvthid<<<dim3(512, 16), 256>>>(hid);
    }

    k_scores_h<<<256, 256>>>();
    k_softmax<<<B_ * R_, 256>>>();
    k_ctxraw_h<<<dim3(8, 16, 2), 256>>>();
    k_ctx<<<dim3(16, 8), 256>>>(ipw);
    k_ctxred<<<512, 256>>>(ipb);
    k_pool_h<<<dim3(8, 2), 256>>>();
    k_sum<<<NROWP, 256>>>(hid, qry, ob, pg, pb, vg, vb, gg, gb);
    k_vg_h<<<dim3(10, 8, 2), 256>>>(bv, bg);
    int wm = (out_size >= NROW * D_ + NROW) ? 1 : 0;
    k_out<<<(NROW * D_ + 255) / 256, 256>>>(out, wm);

    if (s1) cudaStreamDestroy(s1);
    if (s2) cudaStreamDestroy(s2);
    if (evRoot) cudaEventDestroy(evRoot);
    if (evA) cudaEventDestroy(evA);
    if (evW) cudaEventDestroy(evW);
}